// round 1
// baseline (speedup 1.0000x reference)
#include <cuda_runtime.h>
#include <cuda_bf16.h>
#include <math.h>

#define S 4096
#define D 768
#define H 12
#define DH 64
#define L 12
#define FF 3072
#define W 256
#define OUT 256

// ---------------- scratch (device globals; no allocations allowed) ----------------
__device__ float g_h[S * D];
__device__ float g_q[S * D];
__device__ float g_k[S * D];
__device__ float g_v[S * D];
__device__ float g_a[S * D];
__device__ float g_t[S * D];
__device__ float g_f[S * FF];

// ---------------- block reduction helper ----------------
__device__ __forceinline__ float block_sum_256(float v) {
    __shared__ float red[8];
    int lane = threadIdx.x & 31;
    int wid = threadIdx.x >> 5;
#pragma unroll
    for (int o = 16; o > 0; o >>= 1) v += __shfl_down_sync(0xffffffffu, v, o);
    if (lane == 0) red[wid] = v;
    __syncthreads();
    if (wid == 0) {
        v = (lane < 8) ? red[lane] : 0.0f;
#pragma unroll
        for (int o = 4; o > 0; o >>= 1) v += __shfl_down_sync(0xffffffffu, v, o);
        if (lane == 0) red[0] = v;
    }
    __syncthreads();
    v = red[0];
    __syncthreads();
    return v;
}

// ---------------- embedding ----------------
__global__ void emb_kernel(const int* __restrict__ x, const float* __restrict__ we,
                           const float* __restrict__ pe, const float* __restrict__ tt,
                           float* __restrict__ out) {
    int s = blockIdx.x;
    int w = x[s];
    const float* wrow = we + (long long)w * D;
    const float* prow = pe + (long long)(s + 2) * D;
    for (int d = threadIdx.x; d < D; d += 256)
        out[s * D + d] = wrow[d] + prow[d] + tt[d];
}

// ---------------- layernorm (row per block) ----------------
__global__ void ln_kernel(const float* __restrict__ in, const float* __restrict__ g,
                          const float* __restrict__ b, float* __restrict__ out) {
    int row = blockIdx.x;
    const float* x = in + row * D;
    float lsum = 0.0f;
    for (int d = threadIdx.x; d < D; d += 256) lsum += x[d];
    float mu = block_sum_256(lsum) * (1.0f / D);
    float lvar = 0.0f;
    for (int d = threadIdx.x; d < D; d += 256) {
        float t = x[d] - mu;
        lvar += t * t;
    }
    float var = block_sum_256(lvar) * (1.0f / D);
    float inv = rsqrtf(var + 1e-5f);
    for (int d = threadIdx.x; d < D; d += 256)
        out[row * D + d] = (x[d] - mu) * inv * g[d] + b[d];
}

// ---------------- SGEMM 128x128x8, 8x8 per thread, 256 threads ----------------
// EPI: 0 = bias, 1 = bias + exact gelu, 2 = bias + residual add
template <int EPI>
__global__ __launch_bounds__(256) void gemm_kernel(const float* __restrict__ A,
                                                   const float* __restrict__ B,
                                                   const float* __restrict__ bias,
                                                   const float* __restrict__ resid,
                                                   float* __restrict__ C, int M, int N,
                                                   int K) {
    const int BM = 128, BN = 128, BK = 8, TM = 8, TN = 8;
    __shared__ float As[BK][BM];
    __shared__ float Bs[BK][BN];
    int tid = threadIdx.x;
    int bx = blockIdx.x;  // N tile
    int by = blockIdx.y;  // M tile

    int arow = tid >> 1;          // 0..127
    int acol = (tid & 1) * 4;     // 0 or 4
    int brow = tid >> 5;          // 0..7
    int bcol = (tid & 31) * 4;    // 0..124

    const float* Aptr = A + (long long)(by * BM + arow) * K + acol;
    const float* Bptr = B + (long long)brow * N + bx * BN + bcol;

    int tr = (tid >> 4) * TM;  // 0..120
    int tc = (tid & 15) * TN;  // 0..120

    float acc[TM][TN];
#pragma unroll
    for (int i = 0; i < TM; i++)
#pragma unroll
        for (int j = 0; j < TN; j++) acc[i][j] = 0.0f;

    for (int k0 = 0; k0 < K; k0 += BK) {
        float4 av = *(const float4*)Aptr;
        float4 bv = *(const float4*)Bptr;
        As[acol + 0][arow] = av.x;
        As[acol + 1][arow] = av.y;
        As[acol + 2][arow] = av.z;
        As[acol + 3][arow] = av.w;
        *(float4*)&Bs[brow][bcol] = bv;
        __syncthreads();
#pragma unroll
        for (int kk = 0; kk < BK; kk++) {
            float4 a0 = *(const float4*)&As[kk][tr];
            float4 a1 = *(const float4*)&As[kk][tr + 4];
            float4 b0 = *(const float4*)&Bs[kk][tc];
            float4 b1 = *(const float4*)&Bs[kk][tc + 4];
            float ar[TM] = {a0.x, a0.y, a0.z, a0.w, a1.x, a1.y, a1.z, a1.w};
            float br[TN] = {b0.x, b0.y, b0.z, b0.w, b1.x, b1.y, b1.z, b1.w};
#pragma unroll
            for (int i = 0; i < TM; i++)
#pragma unroll
                for (int j = 0; j < TN; j++) acc[i][j] += ar[i] * br[j];
        }
        __syncthreads();
        Aptr += BK;
        Bptr += (long long)BK * N;
    }

    int crow0 = by * BM + tr;
    int ccol0 = bx * BN + tc;
#pragma unroll
    for (int i = 0; i < TM; i++) {
        long long rbase = (long long)(crow0 + i) * N + ccol0;
#pragma unroll
        for (int j = 0; j < TN; j++) {
            float v = acc[i][j] + bias[ccol0 + j];
            if (EPI == 1) v = 0.5f * v * (1.0f + erff(v * 0.70710678118654752f));
            if (EPI == 2) v += resid[rbase + j];
            C[rbase + j] = v;
        }
    }
}

// ---------------- sliding-window attention ----------------
// grid: (chunks=16, heads=12); 256 threads; one thread = one query row.
// Online softmax over the 768-key window, K/V staged in smem 32 keys at a time.
__global__ __launch_bounds__(256, 1) void attn_kernel(const float* __restrict__ q,
                                                      const float* __restrict__ k,
                                                      const float* __restrict__ v,
                                                      float* __restrict__ a) {
    const int KT = 32;
    __shared__ float Ks[KT][DH];
    __shared__ float Vs[KT][DH];

    int c = blockIdx.x;   // chunk
    int h = blockIdx.y;   // head
    int i = threadIdx.x;  // query within chunk
    int qi = c * W + i;
    int base = c * W - W;  // global index of window key j=0

    float qreg[DH];
    const float* qp = q + (long long)qi * D + h * DH;
#pragma unroll
    for (int d = 0; d < DH; d++) qreg[d] = qp[d] * 0.125f;  // 1/sqrt(64)

    float m = -1e30f, l = 0.0f;
    float acc[DH];
#pragma unroll
    for (int d = 0; d < DH; d++) acc[d] = 0.0f;

    for (int t = 0; t < (3 * W) / KT; t++) {
        int j0 = t * KT;
        // cooperative load of KT x 64 K and V tiles (2 float4 per thread per tile)
#pragma unroll
        for (int u = 0; u < 2; u++) {
            int f4 = u * 256 + i;         // 0..511
            int r = f4 >> 4;              // 0..31
            int c4 = (f4 & 15) * 4;       // 0..60
            int kg = base + j0 + r;
            float4 kv = make_float4(0.f, 0.f, 0.f, 0.f);
            float4 vv = kv;
            if (kg >= 0 && kg < S) {
                kv = *(const float4*)(k + (long long)kg * D + h * DH + c4);
                vv = *(const float4*)(v + (long long)kg * D + h * DH + c4);
            }
            *(float4*)&Ks[r][c4] = kv;
            *(float4*)&Vs[r][c4] = vv;
        }
        __syncthreads();

        float sreg[KT];
        float tmax = -1e30f;
#pragma unroll
        for (int j = 0; j < KT; j++) {
            float dot = 0.0f;
#pragma unroll
            for (int d = 0; d < DH; d++) dot += qreg[d] * Ks[j][d];
            int jg = j0 + j;
            int kg = base + jg;
            bool ok = (jg >= i) && (jg <= i + 2 * W) && (kg >= 0) && (kg < S);
            sreg[j] = ok ? dot : -1e30f;
            tmax = fmaxf(tmax, sreg[j]);
        }
        if (tmax > -1e29f) {
            float mnew = fmaxf(m, tmax);
            float scale = __expf(m - mnew);
            l *= scale;
#pragma unroll
            for (int d = 0; d < DH; d++) acc[d] *= scale;
#pragma unroll
            for (int j = 0; j < KT; j++) {
                float p = __expf(sreg[j] - mnew);
                l += p;
#pragma unroll
                for (int d = 0; d < DH; d++) acc[d] += p * Vs[j][d];
            }
            m = mnew;
        }
        __syncthreads();
    }

    float invl = 1.0f / l;
    float* ap = a + (long long)qi * D + h * DH;
#pragma unroll
    for (int d = 0; d < DH; d++) ap[d] = acc[d] * invl;
}

// ---------------- output head: out = h[0,:] @ out_w + out_b ----------------
__global__ void head_kernel(const float* __restrict__ hrow, const float* __restrict__ w,
                            const float* __restrict__ b, float* __restrict__ out) {
    int o = threadIdx.x;  // 0..255
    float acc = b[o];
    for (int d = 0; d < D; d++) acc += hrow[d] * w[d * OUT + o];
    out[o] = acc;
}

// ---------------- launch ----------------
extern "C" void kernel_launch(void* const* d_in, const int* in_sizes, int n_in,
                              void* d_out, int out_size) {
    const int* x = (const int*)d_in[0];
    const float* word_emb = (const float*)d_in[1];
    const float* pos_emb = (const float*)d_in[2];
    const float* tt_emb = (const float*)d_in[3];
    const float* elg = (const float*)d_in[4];
    const float* elb = (const float*)d_in[5];
    const float* Wq = (const float*)d_in[6];
    const float* bq = (const float*)d_in[7];
    const float* Wk = (const float*)d_in[8];
    const float* bk = (const float*)d_in[9];
    const float* Wv = (const float*)d_in[10];
    const float* bv = (const float*)d_in[11];
    const float* Wo = (const float*)d_in[12];
    const float* bo = (const float*)d_in[13];
    const float* g1 = (const float*)d_in[14];
    const float* b1 = (const float*)d_in[15];
    const float* Wi = (const float*)d_in[16];
    const float* bi = (const float*)d_in[17];
    const float* Wd = (const float*)d_in[18];
    const float* bd = (const float*)d_in[19];
    const float* g2 = (const float*)d_in[20];
    const float* b2 = (const float*)d_in[21];
    const float* ow = (const float*)d_in[22];
    const float* ob = (const float*)d_in[23];
    float* out = (float*)d_out;

    float *h, *q, *k, *v, *a, *t, *f;
    cudaGetSymbolAddress((void**)&h, g_h);
    cudaGetSymbolAddress((void**)&q, g_q);
    cudaGetSymbolAddress((void**)&k, g_k);
    cudaGetSymbolAddress((void**)&v, g_v);
    cudaGetSymbolAddress((void**)&a, g_a);
    cudaGetSymbolAddress((void**)&t, g_t);
    cudaGetSymbolAddress((void**)&f, g_f);

    emb_kernel<<<S, 256>>>(x, word_emb, pos_emb, tt_emb, t);
    ln_kernel<<<S, 256>>>(t, elg, elb, h);

    dim3 gproj(D / 128, S / 128);    // 6 x 32
    dim3 gff1(FF / 128, S / 128);    // 24 x 32
    dim3 gattn(S / W, H);            // 16 x 12

    for (int l = 0; l < L; l++) {
        const float* wq = Wq + (long long)l * D * D;
        const float* wk = Wk + (long long)l * D * D;
        const float* wv = Wv + (long long)l * D * D;
        const float* wo = Wo + (long long)l * D * D;
        const float* wi = Wi + (long long)l * D * FF;
        const float* wd = Wd + (long long)l * FF * D;

        gemm_kernel<0><<<gproj, 256>>>(h, wq, bq + l * D, nullptr, q, S, D, D);
        gemm_kernel<0><<<gproj, 256>>>(h, wk, bk + l * D, nullptr, k, S, D, D);
        gemm_kernel<0><<<gproj, 256>>>(h, wv, bv + l * D, nullptr, v, S, D, D);

        attn_kernel<<<gattn, 256>>>(q, k, v, a);

        gemm_kernel<2><<<gproj, 256>>>(a, wo, bo + l * D, h, t, S, D, D);
        ln_kernel<<<S, 256>>>(t, g1 + l * D, b1 + l * D, h);

        gemm_kernel<1><<<gff1, 256>>>(h, wi, bi + l * FF, nullptr, f, S, FF, D);
        gemm_kernel<2><<<gproj, 256>>>(f, wd, bd + l * D, h, t, S, D, FF);
        ln_kernel<<<S, 256>>>(t, g2 + l * D, b2 + l * D, h);
    }

    head_kernel<<<1, 256>>>(h, ow, ob, out);
}

// round 3
// speedup vs baseline: 1.5460x; 1.5460x over previous
#include <cuda_runtime.h>
#include <cuda_bf16.h>
#include <math.h>
#include <stdint.h>

#define S 4096
#define D 768
#define H 12
#define DH 64
#define L 12
#define FF 3072
#define W 256
#define OUT 256

// ---------------- scratch (device globals; no allocations allowed) ----------------
__device__ float g_h[S * D];
__device__ float g_q[S * D];
__device__ float g_k[S * D];
__device__ float g_v[S * D];
__device__ float g_a[S * D];
__device__ float g_t[S * D];
__device__ float g_f[S * FF];
#define WT_PER_LAYER (4 * D * D + 2 * D * FF)
__device__ __nv_bfloat16 g_wTh[L * WT_PER_LAYER];  // transposed weight hi plane [N][K]
__device__ __nv_bfloat16 g_wTl[L * WT_PER_LAYER];  // transposed weight lo plane [N][K]

// ================= helpers =================
__device__ __forceinline__ uint32_t smem_u32(const void* p) {
    uint32_t a;
    asm("{ .reg .u64 t; cvta.to.shared.u64 t, %1; cvt.u32.u64 %0, t; }" : "=r"(a) : "l"(p));
    return a;
}
#define SWZ128(off) ((off) ^ (((off) >> 3) & 0x70))

#define LDSM_X4(r, addr)                                                          \
    asm volatile("ldmatrix.sync.aligned.m8n8.x4.shared.b16 {%0,%1,%2,%3}, [%4];" \
                 : "=r"((r)[0]), "=r"((r)[1]), "=r"((r)[2]), "=r"((r)[3])         \
                 : "r"(addr))

#define MMA_BF16(d, a, b0, b1)                                                     \
    asm volatile(                                                                  \
        "mma.sync.aligned.m16n8k16.row.col.f32.bf16.bf16.f32 "                     \
        "{%0,%1,%2,%3}, {%4,%5,%6,%7}, {%8,%9}, {%0,%1,%2,%3};"                    \
        : "+f"((d)[0]), "+f"((d)[1]), "+f"((d)[2]), "+f"((d)[3])                   \
        : "r"((a)[0]), "r"((a)[1]), "r"((a)[2]), "r"((a)[3]), "r"(b0), "r"(b1))

// ================= small kernels =================
__device__ __forceinline__ float block_sum_256(float v) {
    __shared__ float red[8];
    int lane = threadIdx.x & 31, wid = threadIdx.x >> 5;
#pragma unroll
    for (int o = 16; o > 0; o >>= 1) v += __shfl_down_sync(0xffffffffu, v, o);
    if (lane == 0) red[wid] = v;
    __syncthreads();
    if (wid == 0) {
        v = (lane < 8) ? red[lane] : 0.0f;
#pragma unroll
        for (int o = 4; o > 0; o >>= 1) v += __shfl_down_sync(0xffffffffu, v, o);
        if (lane == 0) red[0] = v;
    }
    __syncthreads();
    v = red[0];
    __syncthreads();
    return v;
}

__global__ void emb_kernel(const int* __restrict__ x, const float* __restrict__ we,
                           const float* __restrict__ pe, const float* __restrict__ tt,
                           float* __restrict__ out) {
    int s = blockIdx.x;
    int w = x[s];
    const float* wrow = we + (long long)w * D;
    const float* prow = pe + (long long)(s + 2) * D;
    for (int d = threadIdx.x; d < D; d += 256)
        out[s * D + d] = wrow[d] + prow[d] + tt[d];
}

__global__ void ln_kernel(const float* __restrict__ in, const float* __restrict__ g,
                          const float* __restrict__ b, float* __restrict__ out) {
    int row = blockIdx.x;
    const float* x = in + row * D;
    float lsum = 0.0f;
    for (int d = threadIdx.x; d < D; d += 256) lsum += x[d];
    float mu = block_sum_256(lsum) * (1.0f / D);
    float lvar = 0.0f;
    for (int d = threadIdx.x; d < D; d += 256) {
        float t = x[d] - mu;
        lvar += t * t;
    }
    float var = block_sum_256(lvar) * (1.0f / D);
    float inv = rsqrtf(var + 1e-5f);
    for (int d = threadIdx.x; d < D; d += 256)
        out[row * D + d] = (x[d] - mu) * inv * g[d] + b[d];
}

// transpose + bf16-split: in[R][C] fp32 -> outh/outl[C][R] bf16
__global__ void transpose_split_kernel(const float* __restrict__ in,
                                       __nv_bfloat16* __restrict__ outh,
                                       __nv_bfloat16* __restrict__ outl, int R, int Ccols) {
    __shared__ float tile[32][33];
    int c0 = blockIdx.x * 32, r0 = blockIdx.y * 32;
    for (int i = threadIdx.y; i < 32; i += 8)
        tile[i][threadIdx.x] = in[(long long)(r0 + i) * Ccols + c0 + threadIdx.x];
    __syncthreads();
    for (int i = threadIdx.y; i < 32; i += 8) {
        float v = tile[threadIdx.x][i];
        __nv_bfloat16 hv = __float2bfloat16_rn(v);
        __nv_bfloat16 lv = __float2bfloat16_rn(v - __bfloat162float(hv));
        long long o = (long long)(c0 + i) * R + r0 + threadIdx.x;
        outh[o] = hv;
        outl[o] = lv;
    }
}

// ================= bf16x3 tensor-core GEMM (mma.sync) =================
// C[M,N] = A[M,K] @ W, with W^T pre-split into bf16 hi/lo planes [N][K].
#define BM 128
#define BN 128
#define BK 64
#define OFF_AH 0
#define OFF_AL 16384
#define OFF_BH 32768
#define OFF_BL 49152
#define SMEM_GEMM 65536

__device__ __forceinline__ void split_store(char* ph, char* pl, float4 v) {
    __nv_bfloat16 hx = __float2bfloat16_rn(v.x);
    __nv_bfloat16 hy = __float2bfloat16_rn(v.y);
    __nv_bfloat16 hz = __float2bfloat16_rn(v.z);
    __nv_bfloat16 hw = __float2bfloat16_rn(v.w);
    __nv_bfloat16 lx = __float2bfloat16_rn(v.x - __bfloat162float(hx));
    __nv_bfloat16 ly = __float2bfloat16_rn(v.y - __bfloat162float(hy));
    __nv_bfloat16 lz = __float2bfloat16_rn(v.z - __bfloat162float(hz));
    __nv_bfloat16 lw = __float2bfloat16_rn(v.w - __bfloat162float(hw));
    uint2 hu, lu;
    hu.x = ((uint32_t)__bfloat16_as_ushort(hy) << 16) | __bfloat16_as_ushort(hx);
    hu.y = ((uint32_t)__bfloat16_as_ushort(hw) << 16) | __bfloat16_as_ushort(hz);
    lu.x = ((uint32_t)__bfloat16_as_ushort(ly) << 16) | __bfloat16_as_ushort(lx);
    lu.y = ((uint32_t)__bfloat16_as_ushort(lw) << 16) | __bfloat16_as_ushort(lz);
    *(uint2*)ph = hu;
    *(uint2*)pl = lu;
}

// EPI: 0 = bias, 1 = bias + exact gelu, 2 = bias + residual
template <int EPI>
__global__ __launch_bounds__(256, 1) void mgemm(const float* __restrict__ A,
                                                const __nv_bfloat16* __restrict__ Bh_g,
                                                const __nv_bfloat16* __restrict__ Bl_g,
                                                const float* __restrict__ bias,
                                                const float* __restrict__ resid,
                                                float* __restrict__ C, int N, int K) {
    extern __shared__ char smem[];
    uint32_t sb = smem_u32(smem);
    int tid = threadIdx.x;
    int lane = tid & 31;
    int wid = tid >> 5;
    int wm = wid >> 2;   // 0..1
    int wn = wid & 3;    // 0..3
    int m0 = blockIdx.y * BM;
    int n0 = blockIdx.x * BN;

    float acc[4][4][4];
#pragma unroll
    for (int i = 0; i < 4; i++)
#pragma unroll
        for (int j = 0; j < 4; j++)
#pragma unroll
            for (int r = 0; r < 4; r++) acc[i][j][r] = 0.0f;

    const int lrow = lane & 15;
    const int lhalf = lane >> 4;

    for (int t = 0; t < K / BK; t++) {
        // ---- stage A (fp32 -> bf16 hi/lo planes) ----
        const float* Ab = A + (long long)m0 * K + t * BK;
#pragma unroll
        for (int i = 0; i < 8; i++) {
            int f4 = i * 256 + tid;
            int row = f4 >> 4;
            int c4 = (f4 & 15) * 4;
            float4 av = *(const float4*)(Ab + (long long)row * K + c4);
            uint32_t off = SWZ128((uint32_t)(row * 128 + c4 * 2));
            split_store(smem + OFF_AH + off, smem + OFF_AL + off, av);
        }
        // ---- stage B (pre-split bf16 planes, direct copy) ----
        const char* Bhb = (const char*)(Bh_g + (long long)n0 * K + t * BK);
        const char* Blb = (const char*)(Bl_g + (long long)n0 * K + t * BK);
#pragma unroll
        for (int i = 0; i < 4; i++) {
            int ck = i * 256 + tid;      // 16B chunk id (1024 per plane)
            int row = ck >> 3;
            int cb = (ck & 7) * 16;
            uint32_t off = SWZ128((uint32_t)(row * 128 + cb));
            *(uint4*)(smem + OFF_BH + off) = *(const uint4*)(Bhb + (long long)row * (K * 2) + cb);
            *(uint4*)(smem + OFF_BL + off) = *(const uint4*)(Blb + (long long)row * (K * 2) + cb);
        }
        __syncthreads();

        // ---- mma over 4 k16 steps ----
#pragma unroll
        for (int ks = 0; ks < 4; ks++) {
            int kb = ks * 32 + lhalf * 16;  // byte col
            uint32_t ah[4][4], al[4][4], bh[2][4], bl[2][4];
#pragma unroll
            for (int mt = 0; mt < 4; mt++) {
                int r = wm * 64 + mt * 16 + lrow;
                uint32_t off = SWZ128((uint32_t)(r * 128 + kb));
                LDSM_X4(ah[mt], sb + OFF_AH + off);
                LDSM_X4(al[mt], sb + OFF_AL + off);
            }
#pragma unroll
            for (int g2 = 0; g2 < 2; g2++) {
                int r = wn * 32 + g2 * 16 + lrow;
                uint32_t off = SWZ128((uint32_t)(r * 128 + kb));
                LDSM_X4(bh[g2], sb + OFF_BH + off);
                LDSM_X4(bl[g2], sb + OFF_BL + off);
            }
#pragma unroll
            for (int mt = 0; mt < 4; mt++)
#pragma unroll
                for (int j = 0; j < 4; j++) {
                    uint32_t b0h = bh[j >> 1][j & 1], b1h = bh[j >> 1][(j & 1) + 2];
                    uint32_t b0l = bl[j >> 1][j & 1], b1l = bl[j >> 1][(j & 1) + 2];
                    MMA_BF16(acc[mt][j], ah[mt], b0h, b1h);
                    MMA_BF16(acc[mt][j], ah[mt], b0l, b1l);
                    MMA_BF16(acc[mt][j], al[mt], b0h, b1h);
                }
        }
        __syncthreads();
    }

    // ---- epilogue: registers -> global, fused bias/gelu/residual ----
    int g = lane >> 2;
    int tig = lane & 3;
#pragma unroll
    for (int mt = 0; mt < 4; mt++) {
#pragma unroll
        for (int j = 0; j < 4; j++) {
            int col = n0 + wn * 32 + j * 8 + tig * 2;
            float bia0 = bias[col], bia1 = bias[col + 1];
#pragma unroll
            for (int half = 0; half < 2; half++) {
                int row = m0 + wm * 64 + mt * 16 + g + half * 8;
                long long rb = (long long)row * N + col;
                float u0 = acc[mt][j][half * 2 + 0] + bia0;
                float u1 = acc[mt][j][half * 2 + 1] + bia1;
                if (EPI == 1) {
                    u0 = 0.5f * u0 * (1.0f + erff(u0 * 0.70710678118654752f));
                    u1 = 0.5f * u1 * (1.0f + erff(u1 * 0.70710678118654752f));
                }
                if (EPI == 2) {
                    u0 += resid[rb];
                    u1 += resid[rb + 1];
                }
                *(float2*)(&C[rb]) = make_float2(u0, u1);
            }
        }
    }
}

// ================= sliding-window attention =================
__global__ __launch_bounds__(256, 1) void attn_kernel(const float* __restrict__ q,
                                                      const float* __restrict__ k,
                                                      const float* __restrict__ v,
                                                      float* __restrict__ a) {
    const int KT = 32;
    __shared__ float Ks[KT][DH];
    __shared__ float Vs[KT][DH];

    int c = blockIdx.x;
    int h = blockIdx.y;
    int i = threadIdx.x;
    int qi = c * W + i;
    int base = c * W - W;

    float qreg[DH];
    const float* qp = q + (long long)qi * D + h * DH;
#pragma unroll
    for (int d = 0; d < DH; d++) qreg[d] = qp[d] * 0.125f;

    float m = -1e30f, l = 0.0f;
    float acc[DH];
#pragma unroll
    for (int d = 0; d < DH; d++) acc[d] = 0.0f;

    for (int t = 0; t < (3 * W) / KT; t++) {
        int j0 = t * KT;
#pragma unroll
        for (int u = 0; u < 2; u++) {
            int f4 = u * 256 + i;
            int r = f4 >> 4;
            int c4 = (f4 & 15) * 4;
            int kg = base + j0 + r;
            float4 kv = make_float4(0.f, 0.f, 0.f, 0.f);
            float4 vv = kv;
            if (kg >= 0 && kg < S) {
                kv = *(const float4*)(k + (long long)kg * D + h * DH + c4);
                vv = *(const float4*)(v + (long long)kg * D + h * DH + c4);
            }
            *(float4*)&Ks[r][c4] = kv;
            *(float4*)&Vs[r][c4] = vv;
        }
        __syncthreads();

        float sreg[KT];
        float tmax = -1e30f;
#pragma unroll
        for (int j = 0; j < KT; j++) {
            float dot = 0.0f;
#pragma unroll
            for (int d = 0; d < DH; d++) dot += qreg[d] * Ks[j][d];
            int jg = j0 + j;
            int kg = base + jg;
            bool ok = (jg >= i) && (jg <= i + 2 * W) && (kg >= 0) && (kg < S);
            sreg[j] = ok ? dot : -1e30f;
            tmax = fmaxf(tmax, sreg[j]);
        }
        if (tmax > -1e29f) {
            float mnew = fmaxf(m, tmax);
            float scale = __expf(m - mnew);
            l *= scale;
#pragma unroll
            for (int d = 0; d < DH; d++) acc[d] *= scale;
#pragma unroll
            for (int j = 0; j < KT; j++) {
                float p = __expf(sreg[j] - mnew);
                l += p;
#pragma unroll
                for (int d = 0; d < DH; d++) acc[d] += p * Vs[j][d];
            }
            m = mnew;
        }
        __syncthreads();
    }

    float invl = 1.0f / l;
    float* ap = a + (long long)qi * D + h * DH;
#pragma unroll
    for (int d = 0; d < DH; d++) ap[d] = acc[d] * invl;
}

__global__ void head_kernel(const float* __restrict__ hrow, const float* __restrict__ w,
                            const float* __restrict__ b, float* __restrict__ out) {
    int o = threadIdx.x;
    float acc = b[o];
    for (int d = 0; d < D; d++) acc += hrow[d] * w[d * OUT + o];
    out[o] = acc;
}

// ================= launch =================
extern "C" void kernel_launch(void* const* d_in, const int* in_sizes, int n_in,
                              void* d_out, int out_size) {
    (void)in_sizes; (void)n_in; (void)out_size;
    const int* x = (const int*)d_in[0];
    const float* word_emb = (const float*)d_in[1];
    const float* pos_emb = (const float*)d_in[2];
    const float* tt_emb = (const float*)d_in[3];
    const float* elg = (const float*)d_in[4];
    const float* elb = (const float*)d_in[5];
    const float* Wq = (const float*)d_in[6];
    const float* bq = (const float*)d_in[7];
    const float* Wk = (const float*)d_in[8];
    const float* bk = (const float*)d_in[9];
    const float* Wv = (const float*)d_in[10];
    const float* bv = (const float*)d_in[11];
    const float* Wo = (const float*)d_in[12];
    const float* bo = (const float*)d_in[13];
    const float* g1 = (const float*)d_in[14];
    const float* b1 = (const float*)d_in[15];
    const float* Wi = (const float*)d_in[16];
    const float* bi = (const float*)d_in[17];
    const float* Wd = (const float*)d_in[18];
    const float* bd = (const float*)d_in[19];
    const float* g2 = (const float*)d_in[20];
    const float* b2 = (const float*)d_in[21];
    const float* ow = (const float*)d_in[22];
    const float* ob = (const float*)d_in[23];
    float* out = (float*)d_out;

    float *h, *q, *k, *v, *a, *t, *f;
    __nv_bfloat16 *wTh, *wTl;
    cudaGetSymbolAddress((void**)&h, g_h);
    cudaGetSymbolAddress((void**)&q, g_q);
    cudaGetSymbolAddress((void**)&k, g_k);
    cudaGetSymbolAddress((void**)&v, g_v);
    cudaGetSymbolAddress((void**)&a, g_a);
    cudaGetSymbolAddress((void**)&t, g_t);
    cudaGetSymbolAddress((void**)&f, g_f);
    cudaGetSymbolAddress((void**)&wTh, g_wTh);
    cudaGetSymbolAddress((void**)&wTl, g_wTl);

    cudaFuncSetAttribute(mgemm<0>, cudaFuncAttributeMaxDynamicSharedMemorySize, SMEM_GEMM);
    cudaFuncSetAttribute(mgemm<1>, cudaFuncAttributeMaxDynamicSharedMemorySize, SMEM_GEMM);
    cudaFuncSetAttribute(mgemm<2>, cudaFuncAttributeMaxDynamicSharedMemorySize, SMEM_GEMM);

    const long long oq = 0, ok = (long long)D * D, ov = 2LL * D * D, oo = 3LL * D * D;
    const long long oi = 4LL * D * D;             // WiT [FF][D]
    const long long od = oi + (long long)D * FF;  // WdT [D][FF]

    // transpose + split all weights once per launch
    {
        dim3 tb(32, 8);
        dim3 gdd(D / 32, D / 32);
        dim3 gdi(FF / 32, D / 32);
        dim3 gdf(D / 32, FF / 32);
        for (int l = 0; l < L; l++) {
            long long lb = (long long)l * WT_PER_LAYER;
            transpose_split_kernel<<<gdd, tb>>>(Wq + (long long)l * D * D, wTh + lb + oq, wTl + lb + oq, D, D);
            transpose_split_kernel<<<gdd, tb>>>(Wk + (long long)l * D * D, wTh + lb + ok, wTl + lb + ok, D, D);
            transpose_split_kernel<<<gdd, tb>>>(Wv + (long long)l * D * D, wTh + lb + ov, wTl + lb + ov, D, D);
            transpose_split_kernel<<<gdd, tb>>>(Wo + (long long)l * D * D, wTh + lb + oo, wTl + lb + oo, D, D);
            transpose_split_kernel<<<gdi, tb>>>(Wi + (long long)l * D * FF, wTh + lb + oi, wTl + lb + oi, D, FF);
            transpose_split_kernel<<<gdf, tb>>>(Wd + (long long)l * FF * D, wTh + lb + od, wTl + lb + od, FF, D);
        }
    }

    emb_kernel<<<S, 256>>>(x, word_emb, pos_emb, tt_emb, t);
    ln_kernel<<<S, 256>>>(t, elg, elb, h);

    dim3 gproj(D / BN, S / BM);  // 6 x 32
    dim3 gff1(FF / BN, S / BM);  // 24 x 32
    dim3 gattn(S / W, H);        // 16 x 12

    for (int l = 0; l < L; l++) {
        long long lb = (long long)l * WT_PER_LAYER;

        mgemm<0><<<gproj, 256, SMEM_GEMM>>>(h, wTh + lb + oq, wTl + lb + oq, bq + l * D, nullptr, q, D, D);
        mgemm<0><<<gproj, 256, SMEM_GEMM>>>(h, wTh + lb + ok, wTl + lb + ok, bk + l * D, nullptr, k, D, D);
        mgemm<0><<<gproj, 256, SMEM_GEMM>>>(h, wTh + lb + ov, wTl + lb + ov, bv + l * D, nullptr, v, D, D);

        attn_kernel<<<gattn, 256>>>(q, k, v, a);

        mgemm<2><<<gproj, 256, SMEM_GEMM>>>(a, wTh + lb + oo, wTl + lb + oo, bo + l * D, h, t, D, D);
        ln_kernel<<<S, 256>>>(t, g1 + l * D, b1 + l * D, h);

        mgemm<1><<<gff1, 256, SMEM_GEMM>>>(h, wTh + lb + oi, wTl + lb + oi, bi + l * FF, nullptr, f, FF, D);
        mgemm<2><<<gproj, 256, SMEM_GEMM>>>(f, wTh + lb + od, wTl + lb + od, bd + l * D, h, t, D, FF);
        ln_kernel<<<S, 256>>>(t, g2 + l * D, b2 + l * D, h);
    }

    head_kernel<<<1, 256>>>(h, ow, ob, out);
}

// round 4
// speedup vs baseline: 1.9527x; 1.2631x over previous
#include <cuda_runtime.h>
#include <cuda_bf16.h>
#include <math.h>
#include <stdint.h>

#define S 4096
#define D 768
#define H 12
#define DH 64
#define L 12
#define FF 3072
#define W 256
#define OUT 256

// ---------------- scratch (device globals; no allocations allowed) ----------------
__device__ float g_h[S * D];   // fp32 residual stream
__device__ float g_t[S * D];   // fp32 pre-LN temp
__device__ float g_q[S * D];
__device__ float g_k[S * D];
__device__ float g_v[S * D];
__device__ __nv_bfloat16 g_hh[S * D], g_hl[S * D];    // h planes
__device__ __nv_bfloat16 g_ah[S * D], g_al[S * D];    // attention-out planes
__device__ __nv_bfloat16 g_fh[S * FF], g_fl[S * FF];  // gelu-out planes
#define WT_PER_LAYER (4 * D * D + 2 * D * FF)
__device__ __nv_bfloat16 g_wTh[L * WT_PER_LAYER];
__device__ __nv_bfloat16 g_wTl[L * WT_PER_LAYER];

// ================= helpers =================
__device__ __forceinline__ uint32_t smem_u32(const void* p) {
    uint32_t a;
    asm("{ .reg .u64 t; cvta.to.shared.u64 t, %1; cvt.u32.u64 %0, t; }" : "=r"(a) : "l"(p));
    return a;
}
#define SWZ128(off) ((off) ^ (((off) >> 3) & 0x70))

#define LDSM_X4(r, addr)                                                          \
    asm volatile("ldmatrix.sync.aligned.m8n8.x4.shared.b16 {%0,%1,%2,%3}, [%4];" \
                 : "=r"((r)[0]), "=r"((r)[1]), "=r"((r)[2]), "=r"((r)[3])         \
                 : "r"(addr))

#define MMA_BF16(d, a, b0, b1)                                                     \
    asm volatile(                                                                  \
        "mma.sync.aligned.m16n8k16.row.col.f32.bf16.bf16.f32 "                     \
        "{%0,%1,%2,%3}, {%4,%5,%6,%7}, {%8,%9}, {%0,%1,%2,%3};"                    \
        : "+f"((d)[0]), "+f"((d)[1]), "+f"((d)[2]), "+f"((d)[3])                   \
        : "r"((a)[0]), "r"((a)[1]), "r"((a)[2]), "r"((a)[3]), "r"(b0), "r"(b1))

#define CP_ASYNC16(dst, src) \
    asm volatile("cp.async.cg.shared.global [%0], [%1], 16;" ::"r"(dst), "l"(src))
#define CP_COMMIT asm volatile("cp.async.commit_group;" ::: "memory")
#define CP_WAIT(n) asm volatile("cp.async.wait_group %0;" ::"n"(n) : "memory")

__device__ __forceinline__ void split_pair(float u0, float u1, __nv_bfloat16* ph,
                                           __nv_bfloat16* pl) {
    __nv_bfloat16 h0 = __float2bfloat16_rn(u0);
    __nv_bfloat16 h1 = __float2bfloat16_rn(u1);
    __nv_bfloat16 l0 = __float2bfloat16_rn(u0 - __bfloat162float(h0));
    __nv_bfloat16 l1 = __float2bfloat16_rn(u1 - __bfloat162float(h1));
    uint32_t hp = ((uint32_t)__bfloat16_as_ushort(h1) << 16) | __bfloat16_as_ushort(h0);
    uint32_t lp = ((uint32_t)__bfloat16_as_ushort(l1) << 16) | __bfloat16_as_ushort(l0);
    *(uint32_t*)ph = hp;
    *(uint32_t*)pl = lp;
}

// ================= small kernels =================
__device__ __forceinline__ float block_sum_256(float v) {
    __shared__ float red[8];
    int lane = threadIdx.x & 31, wid = threadIdx.x >> 5;
#pragma unroll
    for (int o = 16; o > 0; o >>= 1) v += __shfl_down_sync(0xffffffffu, v, o);
    if (lane == 0) red[wid] = v;
    __syncthreads();
    if (wid == 0) {
        v = (lane < 8) ? red[lane] : 0.0f;
#pragma unroll
        for (int o = 4; o > 0; o >>= 1) v += __shfl_down_sync(0xffffffffu, v, o);
        if (lane == 0) red[0] = v;
    }
    __syncthreads();
    v = red[0];
    __syncthreads();
    return v;
}

__global__ void emb_kernel(const int* __restrict__ x, const float* __restrict__ we,
                           const float* __restrict__ pe, const float* __restrict__ tt,
                           float* __restrict__ out) {
    int s = blockIdx.x;
    int w = x[s];
    const float* wrow = we + (long long)w * D;
    const float* prow = pe + (long long)(s + 2) * D;
    for (int d = threadIdx.x; d < D; d += 256)
        out[s * D + d] = wrow[d] + prow[d] + tt[d];
}

// LayerNorm -> fp32 out + bf16 hi/lo planes
__global__ void ln_kernel(const float* __restrict__ in, const float* __restrict__ g,
                          const float* __restrict__ b, float* __restrict__ out,
                          __nv_bfloat16* __restrict__ outh, __nv_bfloat16* __restrict__ outl) {
    int row = blockIdx.x;
    const float* x = in + row * D;
    float lsum = 0.0f;
    for (int d = threadIdx.x; d < D; d += 256) lsum += x[d];
    float mu = block_sum_256(lsum) * (1.0f / D);
    float lvar = 0.0f;
    for (int d = threadIdx.x; d < D; d += 256) {
        float t = x[d] - mu;
        lvar += t * t;
    }
    float var = block_sum_256(lvar) * (1.0f / D);
    float inv = rsqrtf(var + 1e-5f);
    for (int d = threadIdx.x; d < D; d += 256) {
        float y = (x[d] - mu) * inv * g[d] + b[d];
        out[row * D + d] = y;
        __nv_bfloat16 hv = __float2bfloat16_rn(y);
        outh[row * D + d] = hv;
        outl[row * D + d] = __float2bfloat16_rn(y - __bfloat162float(hv));
    }
}

// transpose + bf16-split: in[R][C] fp32 -> outh/outl[C][R] bf16
__global__ void transpose_split_kernel(const float* __restrict__ in,
                                       __nv_bfloat16* __restrict__ outh,
                                       __nv_bfloat16* __restrict__ outl, int R, int Ccols) {
    __shared__ float tile[32][33];
    int c0 = blockIdx.x * 32, r0 = blockIdx.y * 32;
    for (int i = threadIdx.y; i < 32; i += 8)
        tile[i][threadIdx.x] = in[(long long)(r0 + i) * Ccols + c0 + threadIdx.x];
    __syncthreads();
    for (int i = threadIdx.y; i < 32; i += 8) {
        float v = tile[threadIdx.x][i];
        __nv_bfloat16 hv = __float2bfloat16_rn(v);
        __nv_bfloat16 lv = __float2bfloat16_rn(v - __bfloat162float(hv));
        long long o = (long long)(c0 + i) * R + r0 + threadIdx.x;
        outh[o] = hv;
        outl[o] = lv;
    }
}

// ================= bf16x3 tensor-core GEMM, cp.async double-buffered =================
#define BM 128
#define BN 128
#define BK 64
#define OFF_AH 0
#define OFF_AL 16384
#define OFF_BH 32768
#define OFF_BL 49152
#define STAGE_BYTES 65536
#define SMEM_GEMM (2 * STAGE_BYTES)

// EPI: 0 = bias, qkv 3-way split out (fp32); 1 = bias+gelu -> plane out; 2 = bias+resid (fp32)
template <int EPI>
__global__ __launch_bounds__(256, 1) void mgemm(
    const __nv_bfloat16* __restrict__ Ah_g, const __nv_bfloat16* __restrict__ Al_g,
    const __nv_bfloat16* __restrict__ Bh_g, const __nv_bfloat16* __restrict__ Bl_g,
    const float* __restrict__ b0, const float* __restrict__ b1, const float* __restrict__ b2,
    const float* __restrict__ resid, float* __restrict__ C0, float* __restrict__ C1,
    float* __restrict__ C2, __nv_bfloat16* __restrict__ Coh, __nv_bfloat16* __restrict__ Col,
    int Nst, int K) {
    extern __shared__ char smem[];
    uint32_t sb = smem_u32(smem);
    int tid = threadIdx.x;
    int lane = tid & 31;
    int wid = tid >> 5;
    int wm = wid >> 2;  // 0..1
    int wn = wid & 3;   // 0..3
    int m0 = blockIdx.y * BM;
    int n0 = blockIdx.x * BN;

    const char* Ahb = (const char*)Ah_g + ((long long)m0 * K) * 2;
    const char* Alb = (const char*)Al_g + ((long long)m0 * K) * 2;
    const char* Bhb = (const char*)Bh_g + ((long long)n0 * K) * 2;
    const char* Blb = (const char*)Bl_g + ((long long)n0 * K) * 2;
    const long long rowstride = (long long)K * 2;

    float acc[4][4][4];
#pragma unroll
    for (int i = 0; i < 4; i++)
#pragma unroll
        for (int j = 0; j < 4; j++)
#pragma unroll
            for (int r = 0; r < 4; r++) acc[i][j][r] = 0.0f;

    const int lrow = lane & 15;
    const int lhalf = lane >> 4;
    const int T = K / BK;

    // per-thread load geometry: 1024 16B chunks per plane / 256 threads = 4 each
    int rowa[4], cba[4];
    uint32_t offa[4];
#pragma unroll
    for (int i = 0; i < 4; i++) {
        int ck = i * 256 + tid;
        rowa[i] = ck >> 3;
        cba[i] = (ck & 7) * 16;
        offa[i] = SWZ128((uint32_t)(rowa[i] * 128 + cba[i]));
    }

#define LOAD_STAGE(t, s)                                                                   \
    do {                                                                                   \
        uint32_t stg = sb + (s) * STAGE_BYTES;                                             \
        long long kb = (long long)(t) * (BK * 2);                                          \
        _Pragma("unroll") for (int i = 0; i < 4; i++) {                                    \
            long long src = rowa[i] * rowstride + kb + cba[i];                             \
            CP_ASYNC16(stg + OFF_AH + offa[i], Ahb + src);                                 \
            CP_ASYNC16(stg + OFF_AL + offa[i], Alb + src);                                 \
            CP_ASYNC16(stg + OFF_BH + offa[i], Bhb + src);                                 \
            CP_ASYNC16(stg + OFF_BL + offa[i], Blb + src);                                 \
        }                                                                                  \
    } while (0)

    LOAD_STAGE(0, 0);
    CP_COMMIT;

    for (int t = 0; t < T; t++) {
        int s = t & 1;
        if (t + 1 < T) {
            LOAD_STAGE(t + 1, (t + 1) & 1);
            CP_COMMIT;
            CP_WAIT(1);
        } else {
            CP_WAIT(0);
        }
        __syncthreads();

        uint32_t stg = sb + s * STAGE_BYTES;
#pragma unroll
        for (int ks = 0; ks < 4; ks++) {
            int kb = ks * 32 + lhalf * 16;
            uint32_t ah[4][4], al[4][4], bh[2][4], bl[2][4];
#pragma unroll
            for (int mt = 0; mt < 4; mt++) {
                int r = wm * 64 + mt * 16 + lrow;
                uint32_t off = SWZ128((uint32_t)(r * 128 + kb));
                LDSM_X4(ah[mt], stg + OFF_AH + off);
                LDSM_X4(al[mt], stg + OFF_AL + off);
            }
#pragma unroll
            for (int g2 = 0; g2 < 2; g2++) {
                int r = wn * 32 + g2 * 16 + lrow;
                uint32_t off = SWZ128((uint32_t)(r * 128 + kb));
                LDSM_X4(bh[g2], stg + OFF_BH + off);
                LDSM_X4(bl[g2], stg + OFF_BL + off);
            }
#pragma unroll
            for (int mt = 0; mt < 4; mt++)
#pragma unroll
                for (int j = 0; j < 4; j++) {
                    uint32_t b0h = bh[j >> 1][j & 1], b1h = bh[j >> 1][(j & 1) + 2];
                    uint32_t b0l = bl[j >> 1][j & 1], b1l = bl[j >> 1][(j & 1) + 2];
                    MMA_BF16(acc[mt][j], ah[mt], b0h, b1h);
                    MMA_BF16(acc[mt][j], ah[mt], b0l, b1l);
                    MMA_BF16(acc[mt][j], al[mt], b0h, b1h);
                }
        }
        __syncthreads();
    }

    // ---- epilogue ----
    int g = lane >> 2;
    int tig = lane & 3;

    const float* bias = b0;
    float* Cp = C0;
    int ncol0 = n0;
    if (EPI == 0) {
        int mat = n0 / 768;
        bias = (mat == 0) ? b0 : ((mat == 1) ? b1 : b2);
        Cp = (mat == 0) ? C0 : ((mat == 1) ? C1 : C2);
        ncol0 = n0 % 768;
    }
    const int ost = (EPI == 0) ? 768 : Nst;

#pragma unroll
    for (int mt = 0; mt < 4; mt++) {
#pragma unroll
        for (int j = 0; j < 4; j++) {
            int colrel = ncol0 + wn * 32 + j * 8 + tig * 2;
            float bia0 = bias[colrel], bia1 = bias[colrel + 1];
#pragma unroll
            for (int half = 0; half < 2; half++) {
                int row = m0 + wm * 64 + mt * 16 + g + half * 8;
                long long rb = (long long)row * ost + colrel;
                float u0 = acc[mt][j][half * 2 + 0] + bia0;
                float u1 = acc[mt][j][half * 2 + 1] + bia1;
                if (EPI == 1) {
                    u0 = 0.5f * u0 * (1.0f + erff(u0 * 0.70710678118654752f));
                    u1 = 0.5f * u1 * (1.0f + erff(u1 * 0.70710678118654752f));
                    split_pair(u0, u1, Coh + rb, Col + rb);
                } else {
                    if (EPI == 2) {
                        u0 += resid[rb];
                        u1 += resid[rb + 1];
                    }
                    *(float2*)(&Cp[rb]) = make_float2(u0, u1);
                }
            }
        }
    }
}

// ================= sliding-window attention (outputs bf16 hi/lo planes) =================
__global__ __launch_bounds__(256, 1) void attn_kernel(const float* __restrict__ q,
                                                      const float* __restrict__ k,
                                                      const float* __restrict__ v,
                                                      __nv_bfloat16* __restrict__ aoh,
                                                      __nv_bfloat16* __restrict__ aol) {
    const int KT = 32;
    __shared__ float Ks[KT][DH];
    __shared__ float Vs[KT][DH];

    int c = blockIdx.x;
    int h = blockIdx.y;
    int i = threadIdx.x;
    int qi = c * W + i;
    int base = c * W - W;

    float qreg[DH];
    const float* qp = q + (long long)qi * D + h * DH;
#pragma unroll
    for (int d = 0; d < DH; d++) qreg[d] = qp[d] * 0.125f;

    float m = -1e30f, l = 0.0f;
    float acc[DH];
#pragma unroll
    for (int d = 0; d < DH; d++) acc[d] = 0.0f;

    for (int t = 0; t < (3 * W) / KT; t++) {
        int j0 = t * KT;
#pragma unroll
        for (int u = 0; u < 2; u++) {
            int f4 = u * 256 + i;
            int r = f4 >> 4;
            int c4 = (f4 & 15) * 4;
            int kg = base + j0 + r;
            float4 kv = make_float4(0.f, 0.f, 0.f, 0.f);
            float4 vv = kv;
            if (kg >= 0 && kg < S) {
                kv = *(const float4*)(k + (long long)kg * D + h * DH + c4);
                vv = *(const float4*)(v + (long long)kg * D + h * DH + c4);
            }
            *(float4*)&Ks[r][c4] = kv;
            *(float4*)&Vs[r][c4] = vv;
        }
        __syncthreads();

        float sreg[KT];
        float tmax = -1e30f;
#pragma unroll
        for (int j = 0; j < KT; j++) {
            float dot = 0.0f;
#pragma unroll
            for (int d = 0; d < DH; d++) dot += qreg[d] * Ks[j][d];
            int jg = j0 + j;
            int kg = base + jg;
            bool ok = (jg >= i) && (jg <= i + 2 * W) && (kg >= 0) && (kg < S);
            sreg[j] = ok ? dot : -1e30f;
            tmax = fmaxf(tmax, sreg[j]);
        }
        if (tmax > -1e29f) {
            float mnew = fmaxf(m, tmax);
            float scale = __expf(m - mnew);
            l *= scale;
#pragma unroll
            for (int d = 0; d < DH; d++) acc[d] *= scale;
#pragma unroll
            for (int j = 0; j < KT; j++) {
                float p = __expf(sreg[j] - mnew);
                l += p;
#pragma unroll
                for (int d = 0; d < DH; d++) acc[d] += p * Vs[j][d];
            }
            m = mnew;
        }
        __syncthreads();
    }

    float invl = 1.0f / l;
    long long ob = (long long)qi * D + h * DH;
#pragma unroll
    for (int d = 0; d < DH; d += 2)
        split_pair(acc[d] * invl, acc[d + 1] * invl, aoh + ob + d, aol + ob + d);
}

__global__ void head_kernel(const float* __restrict__ hrow, const float* __restrict__ w,
                            const float* __restrict__ b, float* __restrict__ out) {
    int o = threadIdx.x;
    float acc = b[o];
    for (int d = 0; d < D; d++) acc += hrow[d] * w[d * OUT + o];
    out[o] = acc;
}

// ================= launch =================
extern "C" void kernel_launch(void* const* d_in, const int* in_sizes, int n_in,
                              void* d_out, int out_size) {
    (void)in_sizes; (void)n_in; (void)out_size;
    const int* x = (const int*)d_in[0];
    const float* word_emb = (const float*)d_in[1];
    const float* pos_emb = (const float*)d_in[2];
    const float* tt_emb = (const float*)d_in[3];
    const float* elg = (const float*)d_in[4];
    const float* elb = (const float*)d_in[5];
    const float* Wq = (const float*)d_in[6];
    const float* bq = (const float*)d_in[7];
    const float* Wk = (const float*)d_in[8];
    const float* bk = (const float*)d_in[9];
    const float* Wv = (const float*)d_in[10];
    const float* bv = (const float*)d_in[11];
    const float* Wo = (const float*)d_in[12];
    const float* bo = (const float*)d_in[13];
    const float* g1 = (const float*)d_in[14];
    const float* b1 = (const float*)d_in[15];
    const float* Wi = (const float*)d_in[16];
    const float* bi = (const float*)d_in[17];
    const float* Wd = (const float*)d_in[18];
    const float* bd = (const float*)d_in[19];
    const float* g2 = (const float*)d_in[20];
    const float* b2 = (const float*)d_in[21];
    const float* ow = (const float*)d_in[22];
    const float* ob = (const float*)d_in[23];
    float* out = (float*)d_out;

    float *h, *t, *q, *k, *v;
    __nv_bfloat16 *hh, *hl, *ah, *al, *fh, *fl, *wTh, *wTl;
    cudaGetSymbolAddress((void**)&h, g_h);
    cudaGetSymbolAddress((void**)&t, g_t);
    cudaGetSymbolAddress((void**)&q, g_q);
    cudaGetSymbolAddress((void**)&k, g_k);
    cudaGetSymbolAddress((void**)&v, g_v);
    cudaGetSymbolAddress((void**)&hh, g_hh);
    cudaGetSymbolAddress((void**)&hl, g_hl);
    cudaGetSymbolAddress((void**)&ah, g_ah);
    cudaGetSymbolAddress((void**)&al, g_al);
    cudaGetSymbolAddress((void**)&fh, g_fh);
    cudaGetSymbolAddress((void**)&fl, g_fl);
    cudaGetSymbolAddress((void**)&wTh, g_wTh);
    cudaGetSymbolAddress((void**)&wTl, g_wTl);

    cudaFuncSetAttribute(mgemm<0>, cudaFuncAttributeMaxDynamicSharedMemorySize, SMEM_GEMM);
    cudaFuncSetAttribute(mgemm<1>, cudaFuncAttributeMaxDynamicSharedMemorySize, SMEM_GEMM);
    cudaFuncSetAttribute(mgemm<2>, cudaFuncAttributeMaxDynamicSharedMemorySize, SMEM_GEMM);

    // per-layer transposed plane offsets: QKV concat [2304][768], Wo [768][768],
    // Wi [3072][768], Wd [768][3072]
    const long long oqkv = 0;
    const long long oo = 2304LL * 768;
    const long long oi = oo + 768LL * 768;
    const long long od = oi + 3072LL * 768;

    {
        dim3 tb(32, 8);
        dim3 gdd(D / 32, D / 32);
        dim3 gdi(FF / 32, D / 32);
        dim3 gdf(D / 32, FF / 32);
        for (int l = 0; l < L; l++) {
            long long lb = (long long)l * WT_PER_LAYER;
            transpose_split_kernel<<<gdd, tb>>>(Wq + (long long)l * D * D, wTh + lb + oqkv, wTl + lb + oqkv, D, D);
            transpose_split_kernel<<<gdd, tb>>>(Wk + (long long)l * D * D, wTh + lb + oqkv + 768LL * 768, wTl + lb + oqkv + 768LL * 768, D, D);
            transpose_split_kernel<<<gdd, tb>>>(Wv + (long long)l * D * D, wTh + lb + oqkv + 2LL * 768 * 768, wTl + lb + oqkv + 2LL * 768 * 768, D, D);
            transpose_split_kernel<<<gdd, tb>>>(Wo + (long long)l * D * D, wTh + lb + oo, wTl + lb + oo, D, D);
            transpose_split_kernel<<<gdi, tb>>>(Wi + (long long)l * D * FF, wTh + lb + oi, wTl + lb + oi, D, FF);
            transpose_split_kernel<<<gdf, tb>>>(Wd + (long long)l * FF * D, wTh + lb + od, wTl + lb + od, FF, D);
        }
    }

    emb_kernel<<<S, 256>>>(x, word_emb, pos_emb, tt_emb, t);
    ln_kernel<<<S, 256>>>(t, elg, elb, h, hh, hl);

    dim3 gqkv(2304 / BN, S / BM);  // 18 x 32
    dim3 gproj(D / BN, S / BM);    // 6 x 32
    dim3 gff1(FF / BN, S / BM);    // 24 x 32
    dim3 gattn(S / W, H);          // 16 x 12

    for (int l = 0; l < L; l++) {
        long long lb = (long long)l * WT_PER_LAYER;

        // fused QKV
        mgemm<0><<<gqkv, 256, SMEM_GEMM>>>(hh, hl, wTh + lb + oqkv, wTl + lb + oqkv,
                                           bq + l * D, bk + l * D, bv + l * D, nullptr,
                                           q, k, v, nullptr, nullptr, 768, D);

        attn_kernel<<<gattn, 256>>>(q, k, v, ah, al);

        mgemm<2><<<gproj, 256, SMEM_GEMM>>>(ah, al, wTh + lb + oo, wTl + lb + oo,
                                            bo + l * D, nullptr, nullptr, h,
                                            t, nullptr, nullptr, nullptr, nullptr, 768, D);
        ln_kernel<<<S, 256>>>(t, g1 + l * D, b1 + l * D, h, hh, hl);

        mgemm<1><<<gff1, 256, SMEM_GEMM>>>(hh, hl, wTh + lb + oi, wTl + lb + oi,
                                           bi + l * FF, nullptr, nullptr, nullptr,
                                           nullptr, nullptr, nullptr, fh, fl, FF, D);
        mgemm<2><<<gproj, 256, SMEM_GEMM>>>(fh, fl, wTh + lb + od, wTl + lb + od,
                                            bd + l * D, nullptr, nullptr, h,
                                            t, nullptr, nullptr, nullptr, nullptr, 768, FF);
        ln_kernel<<<S, 256>>>(t, g2 + l * D, b2 + l * D, h, hh, hl);
    }

    head_kernel<<<1, 256>>>(h, ow, ob, out);
}

// round 5
// speedup vs baseline: 2.6810x; 1.3729x over previous
#include <cuda_runtime.h>
#include <cuda_bf16.h>
#include <math.h>
#include <stdint.h>

#define S 4096
#define D 768
#define H 12
#define DH 64
#define L 12
#define FF 3072
#define W 256
#define OUT 256

// ---------------- scratch (device globals; no allocations allowed) ----------------
__device__ float g_h[S * D];  // fp32 residual stream
__device__ float g_t[S * D];  // fp32 pre-LN temp
__device__ __nv_bfloat16 g_qh[S * D], g_ql[S * D];
__device__ __nv_bfloat16 g_kh[S * D], g_kl[S * D];
__device__ __nv_bfloat16 g_vh[S * D], g_vl[S * D];
__device__ __nv_bfloat16 g_hh[S * D], g_hl[S * D];    // h planes
__device__ __nv_bfloat16 g_ah[S * D], g_al[S * D];    // attention-out planes
__device__ __nv_bfloat16 g_fh[S * FF], g_fl[S * FF];  // gelu-out planes
#define WT_PER_LAYER (4 * D * D + 2 * D * FF)
__device__ __nv_bfloat16 g_wTh[L * WT_PER_LAYER];
__device__ __nv_bfloat16 g_wTl[L * WT_PER_LAYER];

// 0.125 * log2(e): folded score scale so softmax can use exp2
#define QSC 0.18033688011112042f

// ================= helpers =================
__device__ __forceinline__ uint32_t smem_u32(const void* p) {
    uint32_t a;
    asm("{ .reg .u64 t; cvta.to.shared.u64 t, %1; cvt.u32.u64 %0, t; }" : "=r"(a) : "l"(p));
    return a;
}
#define SWZ128(off) ((off) ^ (((off) >> 3) & 0x70))

#define LDSM_X4(r, addr)                                                          \
    asm volatile("ldmatrix.sync.aligned.m8n8.x4.shared.b16 {%0,%1,%2,%3}, [%4];" \
                 : "=r"((r)[0]), "=r"((r)[1]), "=r"((r)[2]), "=r"((r)[3])         \
                 : "r"(addr))
#define LDSM_X4_T(r, addr)                                                              \
    asm volatile("ldmatrix.sync.aligned.m8n8.x4.trans.shared.b16 {%0,%1,%2,%3}, [%4];" \
                 : "=r"((r)[0]), "=r"((r)[1]), "=r"((r)[2]), "=r"((r)[3])               \
                 : "r"(addr))

#define MMA_BF16(d, a, b0, b1)                                                     \
    asm volatile(                                                                  \
        "mma.sync.aligned.m16n8k16.row.col.f32.bf16.bf16.f32 "                     \
        "{%0,%1,%2,%3}, {%4,%5,%6,%7}, {%8,%9}, {%0,%1,%2,%3};"                    \
        : "+f"((d)[0]), "+f"((d)[1]), "+f"((d)[2]), "+f"((d)[3])                   \
        : "r"((a)[0]), "r"((a)[1]), "r"((a)[2]), "r"((a)[3]), "r"(b0), "r"(b1))

#define CP_ASYNC16(dst, src) \
    asm volatile("cp.async.cg.shared.global [%0], [%1], 16;" ::"r"(dst), "l"(src))
#define CP_ASYNC16Z(dst, src, sz) \
    asm volatile("cp.async.cg.shared.global [%0], [%1], 16, %2;" ::"r"(dst), "l"(src), "r"(sz))
#define CP_COMMIT asm volatile("cp.async.commit_group;" ::: "memory")
#define CP_WAIT(n) asm volatile("cp.async.wait_group %0;" ::"n"(n) : "memory")

__device__ __forceinline__ void split_pair(float u0, float u1, __nv_bfloat16* ph,
                                           __nv_bfloat16* pl) {
    __nv_bfloat16 h0 = __float2bfloat16_rn(u0);
    __nv_bfloat16 h1 = __float2bfloat16_rn(u1);
    __nv_bfloat16 l0 = __float2bfloat16_rn(u0 - __bfloat162float(h0));
    __nv_bfloat16 l1 = __float2bfloat16_rn(u1 - __bfloat162float(h1));
    uint32_t hp = ((uint32_t)__bfloat16_as_ushort(h1) << 16) | __bfloat16_as_ushort(h0);
    uint32_t lp = ((uint32_t)__bfloat16_as_ushort(l1) << 16) | __bfloat16_as_ushort(l0);
    *(uint32_t*)ph = hp;
    *(uint32_t*)pl = lp;
}
// pack two fp32 into bf16x2 hi plane and lo plane regs
__device__ __forceinline__ void pack_hl(float a, float b, uint32_t& hi, uint32_t& lo) {
    __nv_bfloat16 ha = __float2bfloat16_rn(a);
    __nv_bfloat16 hb = __float2bfloat16_rn(b);
    __nv_bfloat16 la = __float2bfloat16_rn(a - __bfloat162float(ha));
    __nv_bfloat16 lb = __float2bfloat16_rn(b - __bfloat162float(hb));
    hi = ((uint32_t)__bfloat16_as_ushort(hb) << 16) | __bfloat16_as_ushort(ha);
    lo = ((uint32_t)__bfloat16_as_ushort(lb) << 16) | __bfloat16_as_ushort(la);
}

// ================= small kernels =================
__device__ __forceinline__ float block_sum_256(float v) {
    __shared__ float red[8];
    int lane = threadIdx.x & 31, wid = threadIdx.x >> 5;
#pragma unroll
    for (int o = 16; o > 0; o >>= 1) v += __shfl_down_sync(0xffffffffu, v, o);
    if (lane == 0) red[wid] = v;
    __syncthreads();
    if (wid == 0) {
        v = (lane < 8) ? red[lane] : 0.0f;
#pragma unroll
        for (int o = 4; o > 0; o >>= 1) v += __shfl_down_sync(0xffffffffu, v, o);
        if (lane == 0) red[0] = v;
    }
    __syncthreads();
    v = red[0];
    __syncthreads();
    return v;
}

__global__ void emb_kernel(const int* __restrict__ x, const float* __restrict__ we,
                           const float* __restrict__ pe, const float* __restrict__ tt,
                           float* __restrict__ out) {
    int s = blockIdx.x;
    int w = x[s];
    const float* wrow = we + (long long)w * D;
    const float* prow = pe + (long long)(s + 2) * D;
    for (int d = threadIdx.x; d < D; d += 256)
        out[s * D + d] = wrow[d] + prow[d] + tt[d];
}

__global__ void ln_kernel(const float* __restrict__ in, const float* __restrict__ g,
                          const float* __restrict__ b, float* __restrict__ out,
                          __nv_bfloat16* __restrict__ outh, __nv_bfloat16* __restrict__ outl) {
    int row = blockIdx.x;
    const float* x = in + row * D;
    float lsum = 0.0f;
    for (int d = threadIdx.x; d < D; d += 256) lsum += x[d];
    float mu = block_sum_256(lsum) * (1.0f / D);
    float lvar = 0.0f;
    for (int d = threadIdx.x; d < D; d += 256) {
        float t = x[d] - mu;
        lvar += t * t;
    }
    float var = block_sum_256(lvar) * (1.0f / D);
    float inv = rsqrtf(var + 1e-5f);
    for (int d = threadIdx.x; d < D; d += 256) {
        float y = (x[d] - mu) * inv * g[d] + b[d];
        out[row * D + d] = y;
        __nv_bfloat16 hv = __float2bfloat16_rn(y);
        outh[row * D + d] = hv;
        outl[row * D + d] = __float2bfloat16_rn(y - __bfloat162float(hv));
    }
}

__global__ void transpose_split_kernel(const float* __restrict__ in,
                                       __nv_bfloat16* __restrict__ outh,
                                       __nv_bfloat16* __restrict__ outl, int R, int Ccols) {
    __shared__ float tile[32][33];
    int c0 = blockIdx.x * 32, r0 = blockIdx.y * 32;
    for (int i = threadIdx.y; i < 32; i += 8)
        tile[i][threadIdx.x] = in[(long long)(r0 + i) * Ccols + c0 + threadIdx.x];
    __syncthreads();
    for (int i = threadIdx.y; i < 32; i += 8) {
        float v = tile[threadIdx.x][i];
        __nv_bfloat16 hv = __float2bfloat16_rn(v);
        __nv_bfloat16 lv = __float2bfloat16_rn(v - __bfloat162float(hv));
        long long o = (long long)(c0 + i) * R + r0 + threadIdx.x;
        outh[o] = hv;
        outl[o] = lv;
    }
}

// ================= bf16x3 tensor-core GEMM, 3-stage cp.async pipeline =================
#define BM 128
#define BN 128
#define BK 64
#define OFF_AH 0
#define OFF_AL 16384
#define OFF_BH 32768
#define OFF_BL 49152
#define STAGE_BYTES 65536
#define SMEM_GEMM (3 * STAGE_BYTES)

// EPI: 0 = bias, qkv planes out (Q scaled); 1 = bias+gelu -> planes; 2 = bias+resid fp32
template <int EPI>
__global__ __launch_bounds__(256, 1) void mgemm(
    const __nv_bfloat16* __restrict__ Ah_g, const __nv_bfloat16* __restrict__ Al_g,
    const __nv_bfloat16* __restrict__ Bh_g, const __nv_bfloat16* __restrict__ Bl_g,
    const float* __restrict__ b0, const float* __restrict__ b1, const float* __restrict__ b2,
    const float* __restrict__ resid, float* __restrict__ C0,
    __nv_bfloat16* __restrict__ P0h, __nv_bfloat16* __restrict__ P0l,
    __nv_bfloat16* __restrict__ P1h, __nv_bfloat16* __restrict__ P1l,
    __nv_bfloat16* __restrict__ P2h, __nv_bfloat16* __restrict__ P2l, int Nst, int K) {
    extern __shared__ char smem[];
    uint32_t sb = smem_u32(smem);
    int tid = threadIdx.x;
    int lane = tid & 31;
    int wid = tid >> 5;
    int wm = wid >> 2;
    int wn = wid & 3;
    int m0 = blockIdx.y * BM;
    int n0 = blockIdx.x * BN;

    const char* Ahb = (const char*)Ah_g + ((long long)m0 * K) * 2;
    const char* Alb = (const char*)Al_g + ((long long)m0 * K) * 2;
    const char* Bhb = (const char*)Bh_g + ((long long)n0 * K) * 2;
    const char* Blb = (const char*)Bl_g + ((long long)n0 * K) * 2;
    const long long rowstride = (long long)K * 2;

    float acc[4][4][4];
#pragma unroll
    for (int i = 0; i < 4; i++)
#pragma unroll
        for (int j = 0; j < 4; j++)
#pragma unroll
            for (int r = 0; r < 4; r++) acc[i][j][r] = 0.0f;

    const int lrow = lane & 15;
    const int lhalf = lane >> 4;
    const int T = K / BK;

    int rowa[4], cba[4];
    uint32_t offa[4];
#pragma unroll
    for (int i = 0; i < 4; i++) {
        int ck = i * 256 + tid;
        rowa[i] = ck >> 3;
        cba[i] = (ck & 7) * 16;
        offa[i] = SWZ128((uint32_t)(rowa[i] * 128 + cba[i]));
    }

#define LOAD_STAGE(t, s)                                                                   \
    do {                                                                                   \
        uint32_t stg = sb + (s) * STAGE_BYTES;                                             \
        long long kb = (long long)(t) * (BK * 2);                                          \
        _Pragma("unroll") for (int i = 0; i < 4; i++) {                                    \
            long long src = rowa[i] * rowstride + kb + cba[i];                             \
            CP_ASYNC16(stg + OFF_AH + offa[i], Ahb + src);                                 \
            CP_ASYNC16(stg + OFF_AL + offa[i], Alb + src);                                 \
            CP_ASYNC16(stg + OFF_BH + offa[i], Bhb + src);                                 \
            CP_ASYNC16(stg + OFF_BL + offa[i], Blb + src);                                 \
        }                                                                                  \
    } while (0)

    LOAD_STAGE(0, 0);
    CP_COMMIT;
    LOAD_STAGE(1, 1);
    CP_COMMIT;

    for (int t = 0; t < T; t++) {
        if (t + 1 < T) {
            CP_WAIT(1);
        } else {
            CP_WAIT(0);
        }
        __syncthreads();
        if (t + 2 < T) {
            LOAD_STAGE(t + 2, (t + 2) % 3);
            CP_COMMIT;
        }
        uint32_t stg = sb + (t % 3) * STAGE_BYTES;
#pragma unroll
        for (int ks = 0; ks < 4; ks++) {
            int kb = ks * 32 + lhalf * 16;
            uint32_t ah[4][4], al[4][4], bh[2][4], bl[2][4];
#pragma unroll
            for (int mt = 0; mt < 4; mt++) {
                int r = wm * 64 + mt * 16 + lrow;
                uint32_t off = SWZ128((uint32_t)(r * 128 + kb));
                LDSM_X4(ah[mt], stg + OFF_AH + off);
                LDSM_X4(al[mt], stg + OFF_AL + off);
            }
#pragma unroll
            for (int g2 = 0; g2 < 2; g2++) {
                int r = wn * 32 + g2 * 16 + lrow;
                uint32_t off = SWZ128((uint32_t)(r * 128 + kb));
                LDSM_X4(bh[g2], stg + OFF_BH + off);
                LDSM_X4(bl[g2], stg + OFF_BL + off);
            }
#pragma unroll
            for (int mt = 0; mt < 4; mt++)
#pragma unroll
                for (int j = 0; j < 4; j++) {
                    uint32_t b0h = bh[j >> 1][j & 1], b1h = bh[j >> 1][(j & 1) + 2];
                    uint32_t b0l = bl[j >> 1][j & 1], b1l = bl[j >> 1][(j & 1) + 2];
                    MMA_BF16(acc[mt][j], ah[mt], b0h, b1h);
                    MMA_BF16(acc[mt][j], ah[mt], b0l, b1l);
                    MMA_BF16(acc[mt][j], al[mt], b0h, b1h);
                }
        }
        __syncthreads();
    }

    // ---- epilogue ----
    int g = lane >> 2;
    int tig = lane & 3;

    const float* bias = b0;
    __nv_bfloat16 *Poh = P0h, *Pol = P0l;
    int ncol0 = n0;
    int mat = 0;
    if (EPI == 0) {
        mat = n0 / 768;
        ncol0 = n0 % 768;
        bias = (mat == 0) ? b0 : ((mat == 1) ? b1 : b2);
        Poh = (mat == 0) ? P0h : ((mat == 1) ? P1h : P2h);
        Pol = (mat == 0) ? P0l : ((mat == 1) ? P1l : P2l);
    }
    const int ost = (EPI == 0) ? 768 : Nst;

#pragma unroll
    for (int mt = 0; mt < 4; mt++) {
#pragma unroll
        for (int j = 0; j < 4; j++) {
            int colrel = ncol0 + wn * 32 + j * 8 + tig * 2;
            float bia0 = bias[colrel], bia1 = bias[colrel + 1];
#pragma unroll
            for (int half = 0; half < 2; half++) {
                int row = m0 + wm * 64 + mt * 16 + g + half * 8;
                long long rb = (long long)row * ost + colrel;
                float u0 = acc[mt][j][half * 2 + 0] + bia0;
                float u1 = acc[mt][j][half * 2 + 1] + bia1;
                if (EPI == 0) {
                    if (mat == 0) {
                        u0 *= QSC;
                        u1 *= QSC;
                    }
                    split_pair(u0, u1, Poh + rb, Pol + rb);
                } else if (EPI == 1) {
                    u0 = 0.5f * u0 * (1.0f + erff(u0 * 0.70710678118654752f));
                    u1 = 0.5f * u1 * (1.0f + erff(u1 * 0.70710678118654752f));
                    split_pair(u0, u1, Poh + rb, Pol + rb);
                } else {
                    u0 += resid[rb];
                    u1 += resid[rb + 1];
                    *(float2*)(&C0[rb]) = make_float2(u0, u1);
                }
            }
        }
    }
}

// ================= tensor-core sliding-window attention =================
// CTA = (chunk c, head h); 8 warps x 32 query rows = 256 rows; KV tiles of 64.
// smem: Qh[0,32K), Ql[32K,64K), 3 stages of {Kh,Kl,Vh,Vl} 8KB each at 64K + s*32K.
#define AKT 64
#define ANT 12
#define ATT_SMEM (65536 + 3 * 32768)

__global__ __launch_bounds__(256, 1) void attn_tc(
    const __nv_bfloat16* __restrict__ qh, const __nv_bfloat16* __restrict__ ql,
    const __nv_bfloat16* __restrict__ kh, const __nv_bfloat16* __restrict__ kl,
    const __nv_bfloat16* __restrict__ vh, const __nv_bfloat16* __restrict__ vl,
    __nv_bfloat16* __restrict__ aoh, __nv_bfloat16* __restrict__ aol) {
    extern __shared__ char smem[];
    uint32_t sb = smem_u32(smem);
    int tid = threadIdx.x;
    int lane = tid & 31;
    int wid = tid >> 5;
    int c = blockIdx.x;
    int h = blockIdx.y;
    const int cbase = c * W - W;  // kg = cbase + jg
    const int lrow = lane & 15;
    const int lhalf = lane >> 4;
    const int wr0 = wid * 32;

    // ---- load Q planes (256 rows x 128B each) ----
#pragma unroll
    for (int i = 0; i < 8; i++) {
        int id = i * 256 + tid;
        int row = id >> 3;
        int cb = (id & 7) * 16;
        long long gsrc = ((long long)(c * W + row) * D + h * DH) * 2 + cb;
        uint32_t dst = sb + SWZ128((uint32_t)(row * 128 + cb));
        CP_ASYNC16(dst, (const char*)qh + gsrc);
        CP_ASYNC16(dst + 32768, (const char*)ql + gsrc);
    }

#define ATT_LOAD(kt, s)                                                               \
    do {                                                                              \
        uint32_t stb = sb + 65536 + (s) * 32768;                                      \
        _Pragma("unroll") for (int pl_ = 0; pl_ < 4; pl_++) {                         \
            const char* gp = (pl_ == 0)   ? (const char*)kh                           \
                             : (pl_ == 1) ? (const char*)kl                           \
                             : (pl_ == 2) ? (const char*)vh                           \
                                          : (const char*)vl;                          \
            _Pragma("unroll") for (int j_ = 0; j_ < 2; j_++) {                        \
                int rem = j_ * 256 + tid;                                             \
                int row = rem >> 3;                                                   \
                int cb = (rem & 7) * 16;                                              \
                int kg = cbase + (kt) * AKT + row;                                    \
                int ok = (kg >= 0 && kg < S);                                         \
                int kgc = ok ? kg : 0;                                                \
                long long gsrc = ((long long)kgc * D + h * DH) * 2 + cb;              \
                CP_ASYNC16Z(stb + pl_ * 8192 + SWZ128((uint32_t)(row * 128 + cb)),    \
                            gp + gsrc, ok ? 16 : 0);                                  \
            }                                                                         \
        }                                                                             \
    } while (0)

    ATT_LOAD(0, 0);
    CP_COMMIT;  // group0 = Q + tile0
    ATT_LOAD(1, 1);
    CP_COMMIT;  // group1 = tile1

    float acc[2][8][4];
#pragma unroll
    for (int mt = 0; mt < 2; mt++)
#pragma unroll
        for (int nf = 0; nf < 8; nf++)
#pragma unroll
            for (int e = 0; e < 4; e++) acc[mt][nf][e] = 0.0f;
    float mrow[2][2] = {{-1e30f, -1e30f}, {-1e30f, -1e30f}};
    float lrowv[2][2] = {{0.0f, 0.0f}, {0.0f, 0.0f}};

    for (int kt = 0; kt < ANT; kt++) {
        if (kt + 1 < ANT) {
            CP_WAIT(1);
        } else {
            CP_WAIT(0);
        }
        __syncthreads();
        if (kt + 2 < ANT) {
            ATT_LOAD(kt + 2, (kt + 2) % 3);
            CP_COMMIT;
        }
        int jg0 = kt * AKT;
        // per-warp band skip
        if (!((jg0 + AKT > wr0) && (jg0 <= wr0 + 31 + 2 * W))) continue;

        uint32_t stb = sb + 65536 + (kt % 3) * 32768;
        uint32_t KH = stb, KL = stb + 8192, VH = stb + 16384, VL = stb + 24576;

        // ---- scores ----
        float sf[2][8][4];
#pragma unroll
        for (int mt = 0; mt < 2; mt++)
#pragma unroll
            for (int nf = 0; nf < 8; nf++)
#pragma unroll
                for (int e = 0; e < 4; e++) sf[mt][nf][e] = 0.0f;

#pragma unroll
        for (int ks = 0; ks < 4; ks++) {
            int kb = ks * 32 + lhalf * 16;
            uint32_t khf[4][4], klf[4][4];
#pragma unroll
            for (int nf2 = 0; nf2 < 4; nf2++) {
                uint32_t off = SWZ128((uint32_t)((nf2 * 16 + lrow) * 128 + kb));
                LDSM_X4(khf[nf2], KH + off);
                LDSM_X4(klf[nf2], KL + off);
            }
#pragma unroll
            for (int mt = 0; mt < 2; mt++) {
                uint32_t qhf[4], qlf[4];
                uint32_t qoff = SWZ128((uint32_t)((wr0 + mt * 16 + lrow) * 128 + kb));
                LDSM_X4(qhf, sb + qoff);
                LDSM_X4(qlf, sb + 32768 + qoff);
#pragma unroll
                for (int nf2 = 0; nf2 < 4; nf2++)
#pragma unroll
                    for (int hf = 0; hf < 2; hf++) {
                        int nf = nf2 * 2 + hf;
                        uint32_t b0h = khf[nf2][hf], b1h = khf[nf2][hf + 2];
                        uint32_t b0l = klf[nf2][hf], b1l = klf[nf2][hf + 2];
                        MMA_BF16(sf[mt][nf], qhf, b0h, b1h);
                        MMA_BF16(sf[mt][nf], qhf, b0l, b1l);
                        MMA_BF16(sf[mt][nf], qlf, b0h, b1h);
                    }
            }
        }

        // ---- mask + online softmax ----
#pragma unroll
        for (int mt = 0; mt < 2; mt++) {
            int rA = wr0 + mt * 16 + (lane >> 2);
            int rB = rA + 8;
#pragma unroll
            for (int nf = 0; nf < 8; nf++)
#pragma unroll
                for (int e = 0; e < 4; e++) {
                    int col = jg0 + nf * 8 + (lane & 3) * 2 + (e & 1);
                    int row = (e < 2) ? rA : rB;
                    int kg = cbase + col;
                    bool ok = (col >= row) && (col <= row + 2 * W) && (kg >= 0) && (kg < S);
                    if (!ok) sf[mt][nf][e] = -1e30f;
                }
            float mA = -1e30f, mB = -1e30f;
#pragma unroll
            for (int nf = 0; nf < 8; nf++) {
                mA = fmaxf(mA, fmaxf(sf[mt][nf][0], sf[mt][nf][1]));
                mB = fmaxf(mB, fmaxf(sf[mt][nf][2], sf[mt][nf][3]));
            }
            mA = fmaxf(mA, __shfl_xor_sync(0xffffffffu, mA, 1));
            mA = fmaxf(mA, __shfl_xor_sync(0xffffffffu, mA, 2));
            mB = fmaxf(mB, __shfl_xor_sync(0xffffffffu, mB, 1));
            mB = fmaxf(mB, __shfl_xor_sync(0xffffffffu, mB, 2));
            float mnA = fmaxf(mrow[mt][0], mA);
            float mnB = fmaxf(mrow[mt][1], mB);
            float scA = exp2f(mrow[mt][0] - mnA);
            float scB = exp2f(mrow[mt][1] - mnB);
            float sumA = 0.0f, sumB = 0.0f;
#pragma unroll
            for (int nf = 0; nf < 8; nf++) {
                float p0 = exp2f(sf[mt][nf][0] - mnA);
                float p1 = exp2f(sf[mt][nf][1] - mnA);
                float p2 = exp2f(sf[mt][nf][2] - mnB);
                float p3 = exp2f(sf[mt][nf][3] - mnB);
                sf[mt][nf][0] = p0;
                sf[mt][nf][1] = p1;
                sf[mt][nf][2] = p2;
                sf[mt][nf][3] = p3;
                sumA += p0 + p1;
                sumB += p2 + p3;
            }
            sumA += __shfl_xor_sync(0xffffffffu, sumA, 1);
            sumA += __shfl_xor_sync(0xffffffffu, sumA, 2);
            sumB += __shfl_xor_sync(0xffffffffu, sumB, 1);
            sumB += __shfl_xor_sync(0xffffffffu, sumB, 2);
            lrowv[mt][0] = lrowv[mt][0] * scA + sumA;
            lrowv[mt][1] = lrowv[mt][1] * scB + sumB;
#pragma unroll
            for (int of = 0; of < 8; of++) {
                acc[mt][of][0] *= scA;
                acc[mt][of][1] *= scA;
                acc[mt][of][2] *= scB;
                acc[mt][of][3] *= scB;
            }
            mrow[mt][0] = mnA;
            mrow[mt][1] = mnB;
        }

        // ---- P x V ----
#pragma unroll
        for (int ks2 = 0; ks2 < 4; ks2++) {
            uint32_t vhf[4][4], vlf[4][4];
#pragma unroll
            for (int vf2 = 0; vf2 < 4; vf2++) {
                uint32_t off = SWZ128((uint32_t)((ks2 * 16 + lrow) * 128 + vf2 * 32 + lhalf * 16));
                LDSM_X4_T(vhf[vf2], VH + off);
                LDSM_X4_T(vlf[vf2], VL + off);
            }
#pragma unroll
            for (int mt = 0; mt < 2; mt++) {
                const float* s0 = sf[mt][2 * ks2];
                const float* s1 = sf[mt][2 * ks2 + 1];
                uint32_t pah[4], pal[4];
                pack_hl(s0[0], s0[1], pah[0], pal[0]);
                pack_hl(s0[2], s0[3], pah[1], pal[1]);
                pack_hl(s1[0], s1[1], pah[2], pal[2]);
                pack_hl(s1[2], s1[3], pah[3], pal[3]);
#pragma unroll
                for (int vf2 = 0; vf2 < 4; vf2++)
#pragma unroll
                    for (int hf = 0; hf < 2; hf++) {
                        int nf = vf2 * 2 + hf;
                        uint32_t b0h = vhf[vf2][hf * 2], b1h = vhf[vf2][hf * 2 + 1];
                        uint32_t b0l = vlf[vf2][hf * 2], b1l = vlf[vf2][hf * 2 + 1];
                        MMA_BF16(acc[mt][nf], pah, b0h, b1h);
                        MMA_BF16(acc[mt][nf], pah, b0l, b1l);
                        MMA_BF16(acc[mt][nf], pal, b0h, b1h);
                    }
            }
        }
    }

    // ---- epilogue: normalize + split to planes ----
#pragma unroll
    for (int mt = 0; mt < 2; mt++) {
        float invA = 1.0f / lrowv[mt][0];
        float invB = 1.0f / lrowv[mt][1];
        int rA = wr0 + mt * 16 + (lane >> 2);
        long long baseA = (long long)(c * W + rA) * D + h * DH;
        long long baseB = baseA + 8LL * D;
#pragma unroll
        for (int nf = 0; nf < 8; nf++) {
            int col = nf * 8 + (lane & 3) * 2;
            split_pair(acc[mt][nf][0] * invA, acc[mt][nf][1] * invA, aoh + baseA + col,
                       aol + baseA + col);
            split_pair(acc[mt][nf][2] * invB, acc[mt][nf][3] * invB, aoh + baseB + col,
                       aol + baseB + col);
        }
    }
}

__global__ void head_kernel(const float* __restrict__ hrow, const float* __restrict__ w,
                            const float* __restrict__ b, float* __restrict__ out) {
    int o = threadIdx.x;
    float acc = b[o];
    for (int d = 0; d < D; d++) acc += hrow[d] * w[d * OUT + o];
    out[o] = acc;
}

// ================= launch =================
extern "C" void kernel_launch(void* const* d_in, const int* in_sizes, int n_in,
                              void* d_out, int out_size) {
    (void)in_sizes; (void)n_in; (void)out_size;
    const int* x = (const int*)d_in[0];
    const float* word_emb = (const float*)d_in[1];
    const float* pos_emb = (const float*)d_in[2];
    const float* tt_emb = (const float*)d_in[3];
    const float* elg = (const float*)d_in[4];
    const float* elb = (const float*)d_in[5];
    const float* Wq = (const float*)d_in[6];
    const float* bq = (const float*)d_in[7];
    const float* Wk = (const float*)d_in[8];
    const float* bk = (const float*)d_in[9];
    const float* Wv = (const float*)d_in[10];
    const float* bv = (const float*)d_in[11];
    const float* Wo = (const float*)d_in[12];
    const float* bo = (const float*)d_in[13];
    const float* g1 = (const float*)d_in[14];
    const float* b1 = (const float*)d_in[15];
    const float* Wi = (const float*)d_in[16];
    const float* bi = (const float*)d_in[17];
    const float* Wd = (const float*)d_in[18];
    const float* bd = (const float*)d_in[19];
    const float* g2 = (const float*)d_in[20];
    const float* b2 = (const float*)d_in[21];
    const float* ow = (const float*)d_in[22];
    const float* ob = (const float*)d_in[23];
    float* out = (float*)d_out;

    float *h, *t;
    __nv_bfloat16 *qh, *ql, *kh, *kl, *vh, *vl, *hh, *hl, *ah, *al, *fh, *fl, *wTh, *wTl;
    cudaGetSymbolAddress((void**)&h, g_h);
    cudaGetSymbolAddress((void**)&t, g_t);
    cudaGetSymbolAddress((void**)&qh, g_qh);
    cudaGetSymbolAddress((void**)&ql, g_ql);
    cudaGetSymbolAddress((void**)&kh, g_kh);
    cudaGetSymbolAddress((void**)&kl, g_kl);
    cudaGetSymbolAddress((void**)&vh, g_vh);
    cudaGetSymbolAddress((void**)&vl, g_vl);
    cudaGetSymbolAddress((void**)&hh, g_hh);
    cudaGetSymbolAddress((void**)&hl, g_hl);
    cudaGetSymbolAddress((void**)&ah, g_ah);
    cudaGetSymbolAddress((void**)&al, g_al);
    cudaGetSymbolAddress((void**)&fh, g_fh);
    cudaGetSymbolAddress((void**)&fl, g_fl);
    cudaGetSymbolAddress((void**)&wTh, g_wTh);
    cudaGetSymbolAddress((void**)&wTl, g_wTl);

    cudaFuncSetAttribute(mgemm<0>, cudaFuncAttributeMaxDynamicSharedMemorySize, SMEM_GEMM);
    cudaFuncSetAttribute(mgemm<1>, cudaFuncAttributeMaxDynamicSharedMemorySize, SMEM_GEMM);
    cudaFuncSetAttribute(mgemm<2>, cudaFuncAttributeMaxDynamicSharedMemorySize, SMEM_GEMM);
    cudaFuncSetAttribute(attn_tc, cudaFuncAttributeMaxDynamicSharedMemorySize, ATT_SMEM);

    const long long oqkv = 0;
    const long long oo = 2304LL * 768;
    const long long oi = oo + 768LL * 768;
    const long long od = oi + 3072LL * 768;

    {
        dim3 tb(32, 8);
        dim3 gdd(D / 32, D / 32);
        dim3 gdi(FF / 32, D / 32);
        dim3 gdf(D / 32, FF / 32);
        for (int l = 0; l < L; l++) {
            long long lb = (long long)l * WT_PER_LAYER;
            transpose_split_kernel<<<gdd, tb>>>(Wq + (long long)l * D * D, wTh + lb + oqkv, wTl + lb + oqkv, D, D);
            transpose_split_kernel<<<gdd, tb>>>(Wk + (long long)l * D * D, wTh + lb + oqkv + 768LL * 768, wTl + lb + oqkv + 768LL * 768, D, D);
            transpose_split_kernel<<<gdd, tb>>>(Wv + (long long)l * D * D, wTh + lb + oqkv + 2LL * 768 * 768, wTl + lb + oqkv + 2LL * 768 * 768, D, D);
            transpose_split_kernel<<<gdd, tb>>>(Wo + (long long)l * D * D, wTh + lb + oo, wTl + lb + oo, D, D);
            transpose_split_kernel<<<gdi, tb>>>(Wi + (long long)l * D * FF, wTh + lb + oi, wTl + lb + oi, D, FF);
            transpose_split_kernel<<<gdf, tb>>>(Wd + (long long)l * FF * D, wTh + lb + od, wTl + lb + od, FF, D);
        }
    }

    emb_kernel<<<S, 256>>>(x, word_emb, pos_emb, tt_emb, t);
    ln_kernel<<<S, 256>>>(t, elg, elb, h, hh, hl);

    dim3 gqkv(2304 / BN, S / BM);
    dim3 gproj(D / BN, S / BM);
    dim3 gff1(FF / BN, S / BM);
    dim3 gattn(S / W, H);

    for (int l = 0; l < L; l++) {
        long long lb = (long long)l * WT_PER_LAYER;

        mgemm<0><<<gqkv, 256, SMEM_GEMM>>>(hh, hl, wTh + lb + oqkv, wTl + lb + oqkv,
                                           bq + l * D, bk + l * D, bv + l * D, nullptr,
                                           nullptr, qh, ql, kh, kl, vh, vl, 768, D);

        attn_tc<<<gattn, 256, ATT_SMEM>>>(qh, ql, kh, kl, vh, vl, ah, al);

        mgemm<2><<<gproj, 256, SMEM_GEMM>>>(ah, al, wTh + lb + oo, wTl + lb + oo,
                                            bo + l * D, nullptr, nullptr, h, t,
                                            nullptr, nullptr, nullptr, nullptr, nullptr, nullptr,
                                            768, D);
        ln_kernel<<<S, 256>>>(t, g1 + l * D, b1 + l * D, h, hh, hl);

        mgemm<1><<<gff1, 256, SMEM_GEMM>>>(hh, hl, wTh + lb + oi, wTl + lb + oi,
                                           bi + l * FF, nullptr, nullptr, nullptr, nullptr,
                                           fh, fl, nullptr, nullptr, nullptr, nullptr, FF, D);
        mgemm<2><<<gproj, 256, SMEM_GEMM>>>(fh, fl, wTh + lb + od, wTl + lb + od,
                                            bd + l * D, nullptr, nullptr, h, t,
                                            nullptr, nullptr, nullptr, nullptr, nullptr, nullptr,
                                            768, FF);
        ln_kernel<<<S, 256>>>(t, g2 + l * D, b2 + l * D, h, hh, hl);
    }

    head_kernel<<<1, 256>>>(h, ow, ob, out);
}

// round 6
// speedup vs baseline: 2.9963x; 1.1176x over previous
#include <cuda_runtime.h>
#include <cuda_bf16.h>
#include <math.h>
#include <stdint.h>

#define S 4096
#define D 768
#define H 12
#define DH 64
#define L 12
#define FF 3072
#define W 256
#define OUT 256

// ---------------- scratch (device globals; no allocations allowed) ----------------
__device__ float g_h[S * D];  // fp32 residual stream
__device__ float g_t[S * D];  // fp32 pre-LN temp
__device__ __nv_bfloat16 g_qh[S * D], g_ql[S * D];
__device__ __nv_bfloat16 g_kh[S * D], g_kl[S * D];
__device__ __nv_bfloat16 g_vh[S * D], g_vl[S * D];
__device__ __nv_bfloat16 g_hh[S * D], g_hl[S * D];
__device__ __nv_bfloat16 g_ah[S * D], g_al[S * D];
__device__ __nv_bfloat16 g_fh[S * FF], g_fl[S * FF];
#define WT_PER_LAYER (4 * D * D + 2 * D * FF)
__device__ __nv_bfloat16 g_wTh[L * WT_PER_LAYER];
__device__ __nv_bfloat16 g_wTl[L * WT_PER_LAYER];

// 0.125 * log2(e)
#define QSC 0.18033688011112042f

// per-layer transposed plane offsets
#define OQKV 0LL
#define OO (2304LL * 768)
#define OI (OO + 768LL * 768)
#define OD (OI + 3072LL * 768)

// ================= helpers =================
__device__ __forceinline__ uint32_t smem_u32(const void* p) {
    uint32_t a;
    asm("{ .reg .u64 t; cvta.to.shared.u64 t, %1; cvt.u32.u64 %0, t; }" : "=r"(a) : "l"(p));
    return a;
}
#define SWZ128(off) ((off) ^ (((off) >> 3) & 0x70))

#define LDSM_X4(r, addr)                                                          \
    asm volatile("ldmatrix.sync.aligned.m8n8.x4.shared.b16 {%0,%1,%2,%3}, [%4];" \
                 : "=r"((r)[0]), "=r"((r)[1]), "=r"((r)[2]), "=r"((r)[3])         \
                 : "r"(addr))
#define LDSM_X4_T(r, addr)                                                              \
    asm volatile("ldmatrix.sync.aligned.m8n8.x4.trans.shared.b16 {%0,%1,%2,%3}, [%4];" \
                 : "=r"((r)[0]), "=r"((r)[1]), "=r"((r)[2]), "=r"((r)[3])               \
                 : "r"(addr))

#define MMA_BF16(d, a, b0, b1)                                                     \
    asm volatile(                                                                  \
        "mma.sync.aligned.m16n8k16.row.col.f32.bf16.bf16.f32 "                     \
        "{%0,%1,%2,%3}, {%4,%5,%6,%7}, {%8,%9}, {%0,%1,%2,%3};"                    \
        : "+f"((d)[0]), "+f"((d)[1]), "+f"((d)[2]), "+f"((d)[3])                   \
        : "r"((a)[0]), "r"((a)[1]), "r"((a)[2]), "r"((a)[3]), "r"(b0), "r"(b1))

#define CP_ASYNC16(dst, src) \
    asm volatile("cp.async.cg.shared.global [%0], [%1], 16;" ::"r"(dst), "l"(src))
#define CP_ASYNC16Z(dst, src, sz) \
    asm volatile("cp.async.cg.shared.global [%0], [%1], 16, %2;" ::"r"(dst), "l"(src), "r"(sz))
#define CP_COMMIT asm volatile("cp.async.commit_group;" ::: "memory")
#define CP_WAIT(n) asm volatile("cp.async.wait_group %0;" ::"n"(n) : "memory")

__device__ __forceinline__ void split_pair(float u0, float u1, __nv_bfloat16* ph,
                                           __nv_bfloat16* pl) {
    __nv_bfloat16 h0 = __float2bfloat16_rn(u0);
    __nv_bfloat16 h1 = __float2bfloat16_rn(u1);
    __nv_bfloat16 l0 = __float2bfloat16_rn(u0 - __bfloat162float(h0));
    __nv_bfloat16 l1 = __float2bfloat16_rn(u1 - __bfloat162float(h1));
    uint32_t hp = ((uint32_t)__bfloat16_as_ushort(h1) << 16) | __bfloat16_as_ushort(h0);
    uint32_t lp = ((uint32_t)__bfloat16_as_ushort(l1) << 16) | __bfloat16_as_ushort(l0);
    *(uint32_t*)ph = hp;
    *(uint32_t*)pl = lp;
}
__device__ __forceinline__ void pack_hl(float a, float b, uint32_t& hi, uint32_t& lo) {
    __nv_bfloat16 ha = __float2bfloat16_rn(a);
    __nv_bfloat16 hb = __float2bfloat16_rn(b);
    __nv_bfloat16 la = __float2bfloat16_rn(a - __bfloat162float(ha));
    __nv_bfloat16 lb = __float2bfloat16_rn(b - __bfloat162float(hb));
    hi = ((uint32_t)__bfloat16_as_ushort(hb) << 16) | __bfloat16_as_ushort(ha);
    lo = ((uint32_t)__bfloat16_as_ushort(lb) << 16) | __bfloat16_as_ushort(la);
}

// ================= small kernels =================
__device__ __forceinline__ float block_sum_256(float v) {
    __shared__ float red[8];
    int lane = threadIdx.x & 31, wid = threadIdx.x >> 5;
#pragma unroll
    for (int o = 16; o > 0; o >>= 1) v += __shfl_down_sync(0xffffffffu, v, o);
    if (lane == 0) red[wid] = v;
    __syncthreads();
    if (wid == 0) {
        v = (lane < 8) ? red[lane] : 0.0f;
#pragma unroll
        for (int o = 4; o > 0; o >>= 1) v += __shfl_down_sync(0xffffffffu, v, o);
        if (lane == 0) red[0] = v;
    }
    __syncthreads();
    v = red[0];
    __syncthreads();
    return v;
}

__global__ void emb_kernel(const int* __restrict__ x, const float* __restrict__ we,
                           const float* __restrict__ pe, const float* __restrict__ tt,
                           float* __restrict__ out) {
    int s = blockIdx.x;
    int w = x[s];
    const float* wrow = we + (long long)w * D;
    const float* prow = pe + (long long)(s + 2) * D;
    for (int d = threadIdx.x; d < D; d += 256)
        out[s * D + d] = wrow[d] + prow[d] + tt[d];
}

__global__ void ln_kernel(const float* __restrict__ in, const float* __restrict__ g,
                          const float* __restrict__ b, float* __restrict__ out,
                          __nv_bfloat16* __restrict__ outh, __nv_bfloat16* __restrict__ outl) {
    int row = blockIdx.x;
    const float* x = in + row * D;
    float lsum = 0.0f;
    for (int d = threadIdx.x; d < D; d += 256) lsum += x[d];
    float mu = block_sum_256(lsum) * (1.0f / D);
    float lvar = 0.0f;
    for (int d = threadIdx.x; d < D; d += 256) {
        float t = x[d] - mu;
        lvar += t * t;
    }
    float var = block_sum_256(lvar) * (1.0f / D);
    float inv = rsqrtf(var + 1e-5f);
    for (int d = threadIdx.x; d < D; d += 256) {
        float y = (x[d] - mu) * inv * g[d] + b[d];
        out[row * D + d] = y;
        __nv_bfloat16 hv = __float2bfloat16_rn(y);
        outh[row * D + d] = hv;
        outl[row * D + d] = __float2bfloat16_rn(y - __bfloat162float(hv));
    }
}

// ---- batched transpose+split kernels (3 launches total) ----
__device__ __forceinline__ void tsp_body(const float* __restrict__ in,
                                         __nv_bfloat16* __restrict__ outh,
                                         __nv_bfloat16* __restrict__ outl, int R, int Ccols) {
    __shared__ float tile[32][33];
    int c0 = blockIdx.x * 32, r0 = blockIdx.y * 32;
    for (int i = threadIdx.y; i < 32; i += 8)
        tile[i][threadIdx.x] = in[(long long)(r0 + i) * Ccols + c0 + threadIdx.x];
    __syncthreads();
    for (int i = threadIdx.y; i < 32; i += 8) {
        float v = tile[threadIdx.x][i];
        __nv_bfloat16 hv = __float2bfloat16_rn(v);
        __nv_bfloat16 lv = __float2bfloat16_rn(v - __bfloat162float(hv));
        long long o = (long long)(c0 + i) * R + r0 + threadIdx.x;
        outh[o] = hv;
        outl[o] = lv;
    }
}
// all four DxD matrices, z = l*4 + m; m: 0=Wq,1=Wk,2=Wv,3=Wo
__global__ void tsp_dd(const float* __restrict__ Wq, const float* __restrict__ Wk,
                       const float* __restrict__ Wv, const float* __restrict__ Wo,
                       __nv_bfloat16* __restrict__ wTh, __nv_bfloat16* __restrict__ wTl) {
    int l = blockIdx.z >> 2, m = blockIdx.z & 3;
    const float* src = (m == 0 ? Wq : m == 1 ? Wk : m == 2 ? Wv : Wo) + (long long)l * D * D;
    long long dst = (long long)l * WT_PER_LAYER + (m < 3 ? OQKV + (long long)m * D * D : OO);
    tsp_body(src, wTh + dst, wTl + dst, D, D);
}
__global__ void tsp_wi(const float* __restrict__ Wi, __nv_bfloat16* __restrict__ wTh,
                       __nv_bfloat16* __restrict__ wTl) {
    int l = blockIdx.z;
    long long dst = (long long)l * WT_PER_LAYER + OI;
    tsp_body(Wi + (long long)l * D * FF, wTh + dst, wTl + dst, D, FF);
}
__global__ void tsp_wd(const float* __restrict__ Wd, __nv_bfloat16* __restrict__ wTh,
                       __nv_bfloat16* __restrict__ wTl) {
    int l = blockIdx.z;
    long long dst = (long long)l * WT_PER_LAYER + OD;
    tsp_body(Wd + (long long)l * FF * D, wTh + dst, wTl + dst, FF, D);
}

// ================= bf16x3 tensor-core GEMM, 3-stage cp.async pipeline =================
// Template: EPI epilogue, BMT = BM (128 or 64). BN=128, BK=64 fixed.
#define BN 128
#define BK 64

// EPI: 0 = bias, qkv planes out (Q scaled); 1 = bias+gelu -> planes; 2 = bias+resid fp32
template <int EPI, int BMT>
__global__ __launch_bounds__(256, 1) void mgemm(
    const __nv_bfloat16* __restrict__ Ah_g, const __nv_bfloat16* __restrict__ Al_g,
    const __nv_bfloat16* __restrict__ Bh_g, const __nv_bfloat16* __restrict__ Bl_g,
    const float* __restrict__ b0, const float* __restrict__ b1, const float* __restrict__ b2,
    const float* __restrict__ resid, float* __restrict__ C0,
    __nv_bfloat16* __restrict__ P0h, __nv_bfloat16* __restrict__ P0l,
    __nv_bfloat16* __restrict__ P1h, __nv_bfloat16* __restrict__ P1l,
    __nv_bfloat16* __restrict__ P2h, __nv_bfloat16* __restrict__ P2l, int Nst, int K) {
    constexpr int NMT = BMT / 32;              // m16 tiles per warp (4 or 2)
    constexpr int APB = BMT * 128;             // A plane bytes
    constexpr int OFF_AL_ = APB;
    constexpr int OFF_BH_ = 2 * APB;
    constexpr int OFF_BL_ = 2 * APB + 16384;
    constexpr int STG_B = 2 * APB + 32768;     // stage bytes
    constexpr int NAC = BMT / 32;              // A 16B-chunks per thread

    extern __shared__ char smem[];
    uint32_t sb = smem_u32(smem);
    int tid = threadIdx.x;
    int lane = tid & 31;
    int wid = tid >> 5;
    int wm = wid >> 2;
    int wn = wid & 3;
    int m0 = blockIdx.y * BMT;
    int n0 = blockIdx.x * BN;

    const char* Ahb = (const char*)Ah_g + ((long long)m0 * K) * 2;
    const char* Alb = (const char*)Al_g + ((long long)m0 * K) * 2;
    const char* Bhb = (const char*)Bh_g + ((long long)n0 * K) * 2;
    const char* Blb = (const char*)Bl_g + ((long long)n0 * K) * 2;
    const long long rowstride = (long long)K * 2;

    float acc[NMT][4][4];
#pragma unroll
    for (int i = 0; i < NMT; i++)
#pragma unroll
        for (int j = 0; j < 4; j++)
#pragma unroll
            for (int r = 0; r < 4; r++) acc[i][j][r] = 0.0f;

    const int lrow = lane & 15;
    const int lhalf = lane >> 4;
    const int T = K / BK;

    int rowa[NAC], cba[NAC];
    uint32_t offa[NAC];
#pragma unroll
    for (int i = 0; i < NAC; i++) {
        int ck = i * 256 + tid;
        rowa[i] = ck >> 3;
        cba[i] = (ck & 7) * 16;
        offa[i] = SWZ128((uint32_t)(rowa[i] * 128 + cba[i]));
    }
    int rowb[4], cbb[4];
    uint32_t offb[4];
#pragma unroll
    for (int i = 0; i < 4; i++) {
        int ck = i * 256 + tid;
        rowb[i] = ck >> 3;
        cbb[i] = (ck & 7) * 16;
        offb[i] = SWZ128((uint32_t)(rowb[i] * 128 + cbb[i]));
    }

#define LOAD_STAGE(t, s)                                                                   \
    do {                                                                                   \
        uint32_t stg = sb + (s) * STG_B;                                                   \
        long long kb = (long long)(t) * (BK * 2);                                          \
        _Pragma("unroll") for (int i = 0; i < NAC; i++) {                                  \
            long long src = rowa[i] * rowstride + kb + cba[i];                             \
            CP_ASYNC16(stg + offa[i], Ahb + src);                                          \
            CP_ASYNC16(stg + OFF_AL_ + offa[i], Alb + src);                                \
        }                                                                                  \
        _Pragma("unroll") for (int i = 0; i < 4; i++) {                                    \
            long long src = rowb[i] * rowstride + kb + cbb[i];                             \
            CP_ASYNC16(stg + OFF_BH_ + offb[i], Bhb + src);                                \
            CP_ASYNC16(stg + OFF_BL_ + offb[i], Blb + src);                                \
        }                                                                                  \
    } while (0)

    LOAD_STAGE(0, 0);
    CP_COMMIT;
    LOAD_STAGE(1, 1);
    CP_COMMIT;

    for (int t = 0; t < T; t++) {
        if (t + 1 < T) {
            CP_WAIT(1);
        } else {
            CP_WAIT(0);
        }
        __syncthreads();
        if (t + 2 < T) {
            LOAD_STAGE(t + 2, (t + 2) % 3);
            CP_COMMIT;
        }
        uint32_t stg = sb + (t % 3) * STG_B;
#pragma unroll
        for (int ks = 0; ks < 4; ks++) {
            int kb = ks * 32 + lhalf * 16;
            uint32_t ah[NMT][4], al[NMT][4], bh[2][4], bl[2][4];
#pragma unroll
            for (int mt = 0; mt < NMT; mt++) {
                int r = wm * (16 * NMT) + mt * 16 + lrow;
                uint32_t off = SWZ128((uint32_t)(r * 128 + kb));
                LDSM_X4(ah[mt], stg + off);
                LDSM_X4(al[mt], stg + OFF_AL_ + off);
            }
#pragma unroll
            for (int g2 = 0; g2 < 2; g2++) {
                int r = wn * 32 + g2 * 16 + lrow;
                uint32_t off = SWZ128((uint32_t)(r * 128 + kb));
                LDSM_X4(bh[g2], stg + OFF_BH_ + off);
                LDSM_X4(bl[g2], stg + OFF_BL_ + off);
            }
#pragma unroll
            for (int mt = 0; mt < NMT; mt++)
#pragma unroll
                for (int j = 0; j < 4; j++) {
                    uint32_t b0h = bh[j >> 1][j & 1], b1h = bh[j >> 1][(j & 1) + 2];
                    uint32_t b0l = bl[j >> 1][j & 1], b1l = bl[j >> 1][(j & 1) + 2];
                    MMA_BF16(acc[mt][j], ah[mt], b0h, b1h);
                    MMA_BF16(acc[mt][j], ah[mt], b0l, b1l);
                    MMA_BF16(acc[mt][j], al[mt], b0h, b1h);
                }
        }
        __syncthreads();
    }

    // ---- epilogue ----
    int g = lane >> 2;
    int tig = lane & 3;

    const float* bias = b0;
    __nv_bfloat16 *Poh = P0h, *Pol = P0l;
    int ncol0 = n0;
    int mat = 0;
    if (EPI == 0) {
        mat = n0 / 768;
        ncol0 = n0 % 768;
        bias = (mat == 0) ? b0 : ((mat == 1) ? b1 : b2);
        Poh = (mat == 0) ? P0h : ((mat == 1) ? P1h : P2h);
        Pol = (mat == 0) ? P0l : ((mat == 1) ? P1l : P2l);
    }
    const int ost = (EPI == 0) ? 768 : Nst;

#pragma unroll
    for (int mt = 0; mt < NMT; mt++) {
#pragma unroll
        for (int j = 0; j < 4; j++) {
            int colrel = ncol0 + wn * 32 + j * 8 + tig * 2;
            float bia0 = bias[colrel], bia1 = bias[colrel + 1];
#pragma unroll
            for (int half = 0; half < 2; half++) {
                int row = m0 + wm * (16 * NMT) + mt * 16 + g + half * 8;
                long long rb = (long long)row * ost + colrel;
                float u0 = acc[mt][j][half * 2 + 0] + bia0;
                float u1 = acc[mt][j][half * 2 + 1] + bia1;
                if (EPI == 0) {
                    if (mat == 0) {
                        u0 *= QSC;
                        u1 *= QSC;
                    }
                    split_pair(u0, u1, Poh + rb, Pol + rb);
                } else if (EPI == 1) {
                    u0 = 0.5f * u0 * (1.0f + erff(u0 * 0.70710678118654752f));
                    u1 = 0.5f * u1 * (1.0f + erff(u1 * 0.70710678118654752f));
                    split_pair(u0, u1, Poh + rb, Pol + rb);
                } else {
                    u0 += resid[rb];
                    u1 += resid[rb + 1];
                    *(float2*)(&C0[rb]) = make_float2(u0, u1);
                }
            }
        }
    }
}

// ================= tensor-core sliding-window attention =================
#define AKT 64
#define ANT 12
#define ATT_SMEM (65536 + 3 * 32768)

__global__ __launch_bounds__(256, 1) void attn_tc(
    const __nv_bfloat16* __restrict__ qh, const __nv_bfloat16* __restrict__ ql,
    const __nv_bfloat16* __restrict__ kh, const __nv_bfloat16* __restrict__ kl,
    const __nv_bfloat16* __restrict__ vh, const __nv_bfloat16* __restrict__ vl,
    __nv_bfloat16* __restrict__ aoh, __nv_bfloat16* __restrict__ aol) {
    extern __shared__ char smem[];
    uint32_t sb = smem_u32(smem);
    int tid = threadIdx.x;
    int lane = tid & 31;
    int wid = tid >> 5;
    int c = blockIdx.x;
    int h = blockIdx.y;
    const int cbase = c * W - W;
    const int lrow = lane & 15;
    const int lhalf = lane >> 4;
    const int wr0 = wid * 32;

#pragma unroll
    for (int i = 0; i < 8; i++) {
        int id = i * 256 + tid;
        int row = id >> 3;
        int cb = (id & 7) * 16;
        long long gsrc = ((long long)(c * W + row) * D + h * DH) * 2 + cb;
        uint32_t dst = sb + SWZ128((uint32_t)(row * 128 + cb));
        CP_ASYNC16(dst, (const char*)qh + gsrc);
        CP_ASYNC16(dst + 32768, (const char*)ql + gsrc);
    }

#define ATT_LOAD(kt, s)                                                               \
    do {                                                                              \
        uint32_t stb = sb + 65536 + (s) * 32768;                                      \
        _Pragma("unroll") for (int pl_ = 0; pl_ < 4; pl_++) {                         \
            const char* gp = (pl_ == 0)   ? (const char*)kh                           \
                             : (pl_ == 1) ? (const char*)kl                           \
                             : (pl_ == 2) ? (const char*)vh                           \
                                          : (const char*)vl;                          \
            _Pragma("unroll") for (int j_ = 0; j_ < 2; j_++) {                        \
                int rem = j_ * 256 + tid;                                             \
                int row = rem >> 3;                                                   \
                int cb = (rem & 7) * 16;                                              \
                int kg = cbase + (kt) * AKT + row;                                    \
                int ok = (kg >= 0 && kg < S);                                         \
                int kgc = ok ? kg : 0;                                                \
                long long gsrc = ((long long)kgc * D + h * DH) * 2 + cb;              \
                CP_ASYNC16Z(stb + pl_ * 8192 + SWZ128((uint32_t)(row * 128 + cb)),    \
                            gp + gsrc, ok ? 16 : 0);                                  \
            }                                                                         \
        }                                                                             \
    } while (0)

    ATT_LOAD(0, 0);
    CP_COMMIT;
    ATT_LOAD(1, 1);
    CP_COMMIT;

    float acc[2][8][4];
#pragma unroll
    for (int mt = 0; mt < 2; mt++)
#pragma unroll
        for (int nf = 0; nf < 8; nf++)
#pragma unroll
            for (int e = 0; e < 4; e++) acc[mt][nf][e] = 0.0f;
    float mrow[2][2] = {{-1e30f, -1e30f}, {-1e30f, -1e30f}};
    float lrowv[2][2] = {{0.0f, 0.0f}, {0.0f, 0.0f}};

    for (int kt = 0; kt < ANT; kt++) {
        if (kt + 1 < ANT) {
            CP_WAIT(1);
        } else {
            CP_WAIT(0);
        }
        __syncthreads();
        if (kt + 2 < ANT) {
            ATT_LOAD(kt + 2, (kt + 2) % 3);
            CP_COMMIT;
        }
        int jg0 = kt * AKT;
        if (!((jg0 + AKT > wr0) && (jg0 <= wr0 + 31 + 2 * W))) continue;

        uint32_t stb = sb + 65536 + (kt % 3) * 32768;
        uint32_t KH = stb, KL = stb + 8192, VH = stb + 16384, VL = stb + 24576;

        float sf[2][8][4];
#pragma unroll
        for (int mt = 0; mt < 2; mt++)
#pragma unroll
            for (int nf = 0; nf < 8; nf++)
#pragma unroll
                for (int e = 0; e < 4; e++) sf[mt][nf][e] = 0.0f;

#pragma unroll
        for (int ks = 0; ks < 4; ks++) {
            int kb = ks * 32 + lhalf * 16;
            uint32_t khf[4][4], klf[4][4];
#pragma unroll
            for (int nf2 = 0; nf2 < 4; nf2++) {
                uint32_t off = SWZ128((uint32_t)((nf2 * 16 + lrow) * 128 + kb));
                LDSM_X4(khf[nf2], KH + off);
                LDSM_X4(klf[nf2], KL + off);
            }
#pragma unroll
            for (int mt = 0; mt < 2; mt++) {
                uint32_t qhf[4], qlf[4];
                uint32_t qoff = SWZ128((uint32_t)((wr0 + mt * 16 + lrow) * 128 + kb));
                LDSM_X4(qhf, sb + qoff);
                LDSM_X4(qlf, sb + 32768 + qoff);
#pragma unroll
                for (int nf2 = 0; nf2 < 4; nf2++)
#pragma unroll
                    for (int hf = 0; hf < 2; hf++) {
                        int nf = nf2 * 2 + hf;
                        uint32_t b0h = khf[nf2][hf], b1h = khf[nf2][hf + 2];
                        uint32_t b0l = klf[nf2][hf], b1l = klf[nf2][hf + 2];
                        MMA_BF16(sf[mt][nf], qhf, b0h, b1h);
                        MMA_BF16(sf[mt][nf], qhf, b0l, b1l);
                        MMA_BF16(sf[mt][nf], qlf, b0h, b1h);
                    }
            }
        }

#pragma unroll
        for (int mt = 0; mt < 2; mt++) {
            int rA = wr0 + mt * 16 + (lane >> 2);
            int rB = rA + 8;
#pragma unroll
            for (int nf = 0; nf < 8; nf++)
#pragma unroll
                for (int e = 0; e < 4; e++) {
                    int col = jg0 + nf * 8 + (lane & 3) * 2 + (e & 1);
                    int row = (e < 2) ? rA : rB;
                    int kg = cbase + col;
                    bool ok = (col >= row) && (col <= row + 2 * W) && (kg >= 0) && (kg < S);
                    if (!ok) sf[mt][nf][e] = -1e30f;
                }
            float mA = -1e30f, mB = -1e30f;
#pragma unroll
            for (int nf = 0; nf < 8; nf++) {
                mA = fmaxf(mA, fmaxf(sf[mt][nf][0], sf[mt][nf][1]));
                mB = fmaxf(mB, fmaxf(sf[mt][nf][2], sf[mt][nf][3]));
            }
            mA = fmaxf(mA, __shfl_xor_sync(0xffffffffu, mA, 1));
            mA = fmaxf(mA, __shfl_xor_sync(0xffffffffu, mA, 2));
            mB = fmaxf(mB, __shfl_xor_sync(0xffffffffu, mB, 1));
            mB = fmaxf(mB, __shfl_xor_sync(0xffffffffu, mB, 2));
            float mnA = fmaxf(mrow[mt][0], mA);
            float mnB = fmaxf(mrow[mt][1], mB);
            float scA = exp2f(mrow[mt][0] - mnA);
            float scB = exp2f(mrow[mt][1] - mnB);
            float sumA = 0.0f, sumB = 0.0f;
#pragma unroll
            for (int nf = 0; nf < 8; nf++) {
                float p0 = exp2f(sf[mt][nf][0] - mnA);
                float p1 = exp2f(sf[mt][nf][1] - mnA);
                float p2 = exp2f(sf[mt][nf][2] - mnB);
                float p3 = exp2f(sf[mt][nf][3] - mnB);
                sf[mt][nf][0] = p0;
                sf[mt][nf][1] = p1;
                sf[mt][nf][2] = p2;
                sf[mt][nf][3] = p3;
                sumA += p0 + p1;
                sumB += p2 + p3;
            }
            sumA += __shfl_xor_sync(0xffffffffu, sumA, 1);
            sumA += __shfl_xor_sync(0xffffffffu, sumA, 2);
            sumB += __shfl_xor_sync(0xffffffffu, sumB, 1);
            sumB += __shfl_xor_sync(0xffffffffu, sumB, 2);
            lrowv[mt][0] = lrowv[mt][0] * scA + sumA;
            lrowv[mt][1] = lrowv[mt][1] * scB + sumB;
#pragma unroll
            for (int of = 0; of < 8; of++) {
                acc[mt][of][0] *= scA;
                acc[mt][of][1] *= scA;
                acc[mt][of][2] *= scB;
                acc[mt][of][3] *= scB;
            }
            mrow[mt][0] = mnA;
            mrow[mt][1] = mnB;
        }

#pragma unroll
        for (int ks2 = 0; ks2 < 4; ks2++) {
            uint32_t vhf[4][4], vlf[4][4];
#pragma unroll
            for (int vf2 = 0; vf2 < 4; vf2++) {
                uint32_t off = SWZ128((uint32_t)((ks2 * 16 + lrow) * 128 + vf2 * 32 + lhalf * 16));
                LDSM_X4_T(vhf[vf2], VH + off);
                LDSM_X4_T(vlf[vf2], VL + off);
            }
#pragma unroll
            for (int mt = 0; mt < 2; mt++) {
                const float* s0 = sf[mt][2 * ks2];
                const float* s1 = sf[mt][2 * ks2 + 1];
                uint32_t pah[4], pal[4];
                pack_hl(s0[0], s0[1], pah[0], pal[0]);
                pack_hl(s0[2], s0[3], pah[1], pal[1]);
                pack_hl(s1[0], s1[1], pah[2], pal[2]);
                pack_hl(s1[2], s1[3], pah[3], pal[3]);
#pragma unroll
                for (int vf2 = 0; vf2 < 4; vf2++)
#pragma unroll
                    for (int hf = 0; hf < 2; hf++) {
                        int nf = vf2 * 2 + hf;
                        uint32_t b0h = vhf[vf2][hf * 2], b1h = vhf[vf2][hf * 2 + 1];
                        uint32_t b0l = vlf[vf2][hf * 2], b1l = vlf[vf2][hf * 2 + 1];
                        MMA_BF16(acc[mt][nf], pah, b0h, b1h);
                        MMA_BF16(acc[mt][nf], pah, b0l, b1l);
                        MMA_BF16(acc[mt][nf], pal, b0h, b1h);
                    }
            }
        }
    }

#pragma unroll
    for (int mt = 0; mt < 2; mt++) {
        float invA = 1.0f / lrowv[mt][0];
        float invB = 1.0f / lrowv[mt][1];
        int rA = wr0 + mt * 16 + (lane >> 2);
        long long baseA = (long long)(c * W + rA) * D + h * DH;
        long long baseB = baseA + 8LL * D;
#pragma unroll
        for (int nf = 0; nf < 8; nf++) {
            int col = nf * 8 + (lane & 3) * 2;
            split_pair(acc[mt][nf][0] * invA, acc[mt][nf][1] * invA, aoh + baseA + col,
                       aol + baseA + col);
            split_pair(acc[mt][nf][2] * invB, acc[mt][nf][3] * invB, aoh + baseB + col,
                       aol + baseB + col);
        }
    }
}

__global__ void head_kernel(const float* __restrict__ hrow, const float* __restrict__ w,
                            const float* __restrict__ b, float* __restrict__ out) {
    int o = threadIdx.x;
    float acc = b[o];
    for (int d = 0; d < D; d++) acc += hrow[d] * w[d * OUT + o];
    out[o] = acc;
}

// ================= launch =================
#define SMEM_G128 (3 * (2 * 128 * 128 + 32768))
#define SMEM_G64 (3 * (2 * 64 * 128 + 32768))

extern "C" void kernel_launch(void* const* d_in, const int* in_sizes, int n_in,
                              void* d_out, int out_size) {
    (void)in_sizes; (void)n_in; (void)out_size;
    const int* x = (const int*)d_in[0];
    const float* word_emb = (const float*)d_in[1];
    const float* pos_emb = (const float*)d_in[2];
    const float* tt_emb = (const float*)d_in[3];
    const float* elg = (const float*)d_in[4];
    const float* elb = (const float*)d_in[5];
    const float* Wq = (const float*)d_in[6];
    const float* bq = (const float*)d_in[7];
    const float* Wk = (const float*)d_in[8];
    const float* bk = (const float*)d_in[9];
    const float* Wv = (const float*)d_in[10];
    const float* bv = (const float*)d_in[11];
    const float* Wo = (const float*)d_in[12];
    const float* bo = (const float*)d_in[13];
    const float* g1 = (const float*)d_in[14];
    const float* b1 = (const float*)d_in[15];
    const float* Wi = (const float*)d_in[16];
    const float* bi = (const float*)d_in[17];
    const float* Wd = (const float*)d_in[18];
    const float* bd = (const float*)d_in[19];
    const float* g2 = (const float*)d_in[20];
    const float* b2 = (const float*)d_in[21];
    const float* ow = (const float*)d_in[22];
    const float* ob = (const float*)d_in[23];
    float* out = (float*)d_out;

    float *h, *t;
    __nv_bfloat16 *qh, *ql, *kh, *kl, *vh, *vl, *hh, *hl, *ah, *al, *fh, *fl, *wTh, *wTl;
    cudaGetSymbolAddress((void**)&h, g_h);
    cudaGetSymbolAddress((void**)&t, g_t);
    cudaGetSymbolAddress((void**)&qh, g_qh);
    cudaGetSymbolAddress((void**)&ql, g_ql);
    cudaGetSymbolAddress((void**)&kh, g_kh);
    cudaGetSymbolAddress((void**)&kl, g_kl);
    cudaGetSymbolAddress((void**)&vh, g_vh);
    cudaGetSymbolAddress((void**)&vl, g_vl);
    cudaGetSymbolAddress((void**)&hh, g_hh);
    cudaGetSymbolAddress((void**)&hl, g_hl);
    cudaGetSymbolAddress((void**)&ah, g_ah);
    cudaGetSymbolAddress((void**)&al, g_al);
    cudaGetSymbolAddress((void**)&fh, g_fh);
    cudaGetSymbolAddress((void**)&fl, g_fl);
    cudaGetSymbolAddress((void**)&wTh, g_wTh);
    cudaGetSymbolAddress((void**)&wTl, g_wTl);

    cudaFuncSetAttribute(mgemm<0, 128>, cudaFuncAttributeMaxDynamicSharedMemorySize, SMEM_G128);
    cudaFuncSetAttribute(mgemm<1, 128>, cudaFuncAttributeMaxDynamicSharedMemorySize, SMEM_G128);
    cudaFuncSetAttribute(mgemm<2, 64>, cudaFuncAttributeMaxDynamicSharedMemorySize, SMEM_G64);
    cudaFuncSetAttribute(attn_tc, cudaFuncAttributeMaxDynamicSharedMemorySize, ATT_SMEM);

    // batched transpose+split: 3 launches
    {
        dim3 tb(32, 8);
        tsp_dd<<<dim3(D / 32, D / 32, 4 * L), tb>>>(Wq, Wk, Wv, Wo, wTh, wTl);
        tsp_wi<<<dim3(FF / 32, D / 32, L), tb>>>(Wi, wTh, wTl);
        tsp_wd<<<dim3(D / 32, FF / 32, L), tb>>>(Wd, wTh, wTl);
    }

    emb_kernel<<<S, 256>>>(x, word_emb, pos_emb, tt_emb, t);
    ln_kernel<<<S, 256>>>(t, elg, elb, h, hh, hl);

    dim3 gqkv(2304 / BN, S / 128);   // 18 x 32
    dim3 gproj64(768 / BN, S / 64);  // 6 x 64
    dim3 gff1(FF / BN, S / 128);     // 24 x 32
    dim3 gattn(S / W, H);            // 16 x 12

    for (int l = 0; l < L; l++) {
        long long lb = (long long)l * WT_PER_LAYER;

        mgemm<0, 128><<<gqkv, 256, SMEM_G128>>>(hh, hl, wTh + lb + OQKV, wTl + lb + OQKV,
                                                bq + l * D, bk + l * D, bv + l * D, nullptr,
                                                nullptr, qh, ql, kh, kl, vh, vl, 768, D);

        attn_tc<<<gattn, 256, ATT_SMEM>>>(qh, ql, kh, kl, vh, vl, ah, al);

        mgemm<2, 64><<<gproj64, 256, SMEM_G64>>>(ah, al, wTh + lb + OO, wTl + lb + OO,
                                                 bo + l * D, nullptr, nullptr, h, t,
                                                 nullptr, nullptr, nullptr, nullptr, nullptr,
                                                 nullptr, 768, D);
        ln_kernel<<<S, 256>>>(t, g1 + l * D, b1 + l * D, h, hh, hl);

        mgemm<1, 128><<<gff1, 256, SMEM_G128>>>(hh, hl, wTh + lb + OI, wTl + lb + OI,
                                                bi + l * FF, nullptr, nullptr, nullptr, nullptr,
                                                fh, fl, nullptr, nullptr, nullptr, nullptr, FF, D);
        mgemm<2, 64><<<gproj64, 256, SMEM_G64>>>(fh, fl, wTh + lb + OD, wTl + lb + OD,
                                                 bd + l * D, nullptr, nullptr, h, t,
                                                 nullptr, nullptr, nullptr, nullptr, nullptr,
                                                 nullptr, 768, FF);
        ln_kernel<<<S, 256>>>(t, g2 + l * D, b2 + l * D, h, hh, hl);
    }

    head_kernel<<<1, 256>>>(h, ow, ob, out);
}

// round 8
// speedup vs baseline: 3.6225x; 1.2090x over previous
#include <cuda_runtime.h>
#include <cuda_bf16.h>
#include <math.h>
#include <stdint.h>

#define S 4096
#define D 768
#define H 12
#define DH 64
#define L 12
#define FF 3072
#define W 256
#define OUT 256

// ---------------- scratch ----------------
__device__ float g_h[S * D];
__device__ float g_t[S * D];
__device__ __nv_bfloat16 g_qh[S * D], g_ql[S * D];
__device__ __nv_bfloat16 g_kh[S * D], g_kl[S * D];
__device__ __nv_bfloat16 g_vh[S * D], g_vl[S * D];
__device__ __nv_bfloat16 g_hh[S * D], g_hl[S * D];
__device__ __nv_bfloat16 g_ah[S * D], g_al[S * D];
__device__ __nv_bfloat16 g_fh[S * FF], g_fl[S * FF];
#define WT_PER_LAYER (4 * D * D + 2 * D * FF)
__device__ __nv_bfloat16 g_wTh[L * WT_PER_LAYER];
__device__ __nv_bfloat16 g_wTl[L * WT_PER_LAYER];

#define QSC 0.18033688011112042f

#define OQKV 0LL
#define OO (2304LL * 768)
#define OI (OO + 768LL * 768)
#define OD (OI + 3072LL * 768)

// ================= helpers =================
__device__ __forceinline__ uint32_t smem_u32(const void* p) {
    uint32_t a;
    asm("{ .reg .u64 t; cvta.to.shared.u64 t, %1; cvt.u32.u64 %0, t; }" : "=r"(a) : "l"(p));
    return a;
}
#define SWZ128(off) ((off) ^ (((off) >> 3) & 0x70))

#define LDSM_X4(r, addr)                                                          \
    asm volatile("ldmatrix.sync.aligned.m8n8.x4.shared.b16 {%0,%1,%2,%3}, [%4];" \
                 : "=r"((r)[0]), "=r"((r)[1]), "=r"((r)[2]), "=r"((r)[3])         \
                 : "r"(addr))
#define LDSM_X4_T(r, addr)                                                              \
    asm volatile("ldmatrix.sync.aligned.m8n8.x4.trans.shared.b16 {%0,%1,%2,%3}, [%4];" \
                 : "=r"((r)[0]), "=r"((r)[1]), "=r"((r)[2]), "=r"((r)[3])               \
                 : "r"(addr))

#define MMA_BF16(d, a, b0, b1)                                                     \
    asm volatile(                                                                  \
        "mma.sync.aligned.m16n8k16.row.col.f32.bf16.bf16.f32 "                     \
        "{%0,%1,%2,%3}, {%4,%5,%6,%7}, {%8,%9}, {%0,%1,%2,%3};"                    \
        : "+f"((d)[0]), "+f"((d)[1]), "+f"((d)[2]), "+f"((d)[3])                   \
        : "r"((a)[0]), "r"((a)[1]), "r"((a)[2]), "r"((a)[3]), "r"(b0), "r"(b1))

#define CP_ASYNC16(dst, src) \
    asm volatile("cp.async.cg.shared.global [%0], [%1], 16;" ::"r"(dst), "l"(src))
#define CP_ASYNC16Z(dst, src, sz) \
    asm volatile("cp.async.cg.shared.global [%0], [%1], 16, %2;" ::"r"(dst), "l"(src), "r"(sz))
#define CP_COMMIT asm volatile("cp.async.commit_group;" ::: "memory")
#define CP_WAIT(n) asm volatile("cp.async.wait_group %0;" ::"n"(n) : "memory")

__device__ __forceinline__ void split_pair(float u0, float u1, __nv_bfloat16* ph,
                                           __nv_bfloat16* pl) {
    __nv_bfloat16 h0 = __float2bfloat16_rn(u0);
    __nv_bfloat16 h1 = __float2bfloat16_rn(u1);
    __nv_bfloat16 l0 = __float2bfloat16_rn(u0 - __bfloat162float(h0));
    __nv_bfloat16 l1 = __float2bfloat16_rn(u1 - __bfloat162float(h1));
    uint32_t hp = ((uint32_t)__bfloat16_as_ushort(h1) << 16) | __bfloat16_as_ushort(h0);
    uint32_t lp = ((uint32_t)__bfloat16_as_ushort(l1) << 16) | __bfloat16_as_ushort(l0);
    *(uint32_t*)ph = hp;
    *(uint32_t*)pl = lp;
}
__device__ __forceinline__ void pack_hl(float a, float b, uint32_t& hi, uint32_t& lo) {
    __nv_bfloat16 ha = __float2bfloat16_rn(a);
    __nv_bfloat16 hb = __float2bfloat16_rn(b);
    __nv_bfloat16 la = __float2bfloat16_rn(a - __bfloat162float(ha));
    __nv_bfloat16 lb = __float2bfloat16_rn(b - __bfloat162float(hb));
    hi = ((uint32_t)__bfloat16_as_ushort(hb) << 16) | __bfloat16_as_ushort(ha);
    lo = ((uint32_t)__bfloat16_as_ushort(lb) << 16) | __bfloat16_as_ushort(la);
}

// ================= small kernels =================
__device__ __forceinline__ float block_sum_256(float v) {
    __shared__ float red[8];
    int lane = threadIdx.x & 31, wid = threadIdx.x >> 5;
#pragma unroll
    for (int o = 16; o > 0; o >>= 1) v += __shfl_down_sync(0xffffffffu, v, o);
    if (lane == 0) red[wid] = v;
    __syncthreads();
    if (wid == 0) {
        v = (lane < 8) ? red[lane] : 0.0f;
#pragma unroll
        for (int o = 4; o > 0; o >>= 1) v += __shfl_down_sync(0xffffffffu, v, o);
        if (lane == 0) red[0] = v;
    }
    __syncthreads();
    v = red[0];
    __syncthreads();
    return v;
}

__global__ void emb_kernel(const int* __restrict__ x, const float* __restrict__ we,
                           const float* __restrict__ pe, const float* __restrict__ tt,
                           float* __restrict__ out) {
    int s = blockIdx.x;
    int w = x[s];
    const float* wrow = we + (long long)w * D;
    const float* prow = pe + (long long)(s + 2) * D;
    for (int d = threadIdx.x; d < D; d += 256)
        out[s * D + d] = wrow[d] + prow[d] + tt[d];
}

__global__ void ln_kernel(const float* __restrict__ in, const float* __restrict__ g,
                          const float* __restrict__ b, float* __restrict__ out,
                          __nv_bfloat16* __restrict__ outh, __nv_bfloat16* __restrict__ outl) {
    int row = blockIdx.x;
    const float* x = in + row * D;
    float lsum = 0.0f;
    for (int d = threadIdx.x; d < D; d += 256) lsum += x[d];
    float mu = block_sum_256(lsum) * (1.0f / D);
    float lvar = 0.0f;
    for (int d = threadIdx.x; d < D; d += 256) {
        float t = x[d] - mu;
        lvar += t * t;
    }
    float var = block_sum_256(lvar) * (1.0f / D);
    float inv = rsqrtf(var + 1e-5f);
    for (int d = threadIdx.x; d < D; d += 256) {
        float y = (x[d] - mu) * inv * g[d] + b[d];
        out[row * D + d] = y;
        __nv_bfloat16 hv = __float2bfloat16_rn(y);
        outh[row * D + d] = hv;
        outl[row * D + d] = __float2bfloat16_rn(y - __bfloat162float(hv));
    }
}

// ---- batched transpose+split ----
__device__ __forceinline__ void tsp_body(const float* __restrict__ in,
                                         __nv_bfloat16* __restrict__ outh,
                                         __nv_bfloat16* __restrict__ outl, int R, int Ccols) {
    __shared__ float tile[32][33];
    int c0 = blockIdx.x * 32, r0 = blockIdx.y * 32;
    for (int i = threadIdx.y; i < 32; i += 8)
        tile[i][threadIdx.x] = in[(long long)(r0 + i) * Ccols + c0 + threadIdx.x];
    __syncthreads();
    for (int i = threadIdx.y; i < 32; i += 8) {
        float v = tile[threadIdx.x][i];
        __nv_bfloat16 hv = __float2bfloat16_rn(v);
        __nv_bfloat16 lv = __float2bfloat16_rn(v - __bfloat162float(hv));
        long long o = (long long)(c0 + i) * R + r0 + threadIdx.x;
        outh[o] = hv;
        outl[o] = lv;
    }
}
__global__ void tsp_dd(const float* __restrict__ Wq, const float* __restrict__ Wk,
                       const float* __restrict__ Wv, const float* __restrict__ Wo,
                       __nv_bfloat16* __restrict__ wTh, __nv_bfloat16* __restrict__ wTl) {
    int l = blockIdx.z >> 2, m = blockIdx.z & 3;
    const float* src = (m == 0 ? Wq : m == 1 ? Wk : m == 2 ? Wv : Wo) + (long long)l * D * D;
    long long dst = (long long)l * WT_PER_LAYER + (m < 3 ? OQKV + (long long)m * D * D : OO);
    tsp_body(src, wTh + dst, wTl + dst, D, D);
}
__global__ void tsp_wi(const float* __restrict__ Wi, __nv_bfloat16* __restrict__ wTh,
                       __nv_bfloat16* __restrict__ wTl) {
    int l = blockIdx.z;
    long long dst = (long long)l * WT_PER_LAYER + OI;
    tsp_body(Wi + (long long)l * D * FF, wTh + dst, wTl + dst, D, FF);
}
__global__ void tsp_wd(const float* __restrict__ Wd, __nv_bfloat16* __restrict__ wTh,
                       __nv_bfloat16* __restrict__ wTl) {
    int l = blockIdx.z;
    long long dst = (long long)l * WT_PER_LAYER + OD;
    tsp_body(Wd + (long long)l * FF * D, wTh + dst, wTl + dst, FF, D);
}

// ================= bf16x3 GEMM: 64x128 tile, 2-stage, 2 CTAs/SM =================
#define BMT 64
#define BN 128
#define BK 64
#define GOFF_AL 8192
#define GOFF_BH 16384
#define GOFF_BL 32768
#define GSTG 49152
#define SMEM_G (2 * GSTG)

// EPI: 0 = bias -> qkv planes (Q scaled); 1 = bias+gelu -> planes; 2 = bias+resid fp32
template <int EPI>
__global__ __launch_bounds__(256, 2) void mgemm(
    const __nv_bfloat16* __restrict__ Ah_g, const __nv_bfloat16* __restrict__ Al_g,
    const __nv_bfloat16* __restrict__ Bh_g, const __nv_bfloat16* __restrict__ Bl_g,
    const float* __restrict__ b0, const float* __restrict__ b1, const float* __restrict__ b2,
    const float* __restrict__ resid, float* __restrict__ C0,
    __nv_bfloat16* __restrict__ P0h, __nv_bfloat16* __restrict__ P0l,
    __nv_bfloat16* __restrict__ P1h, __nv_bfloat16* __restrict__ P1l,
    __nv_bfloat16* __restrict__ P2h, __nv_bfloat16* __restrict__ P2l, int Nst, int K) {
    extern __shared__ char smem[];
    uint32_t sb = smem_u32(smem);
    int tid = threadIdx.x;
    int lane = tid & 31;
    int wid = tid >> 5;
    int wm = wid >> 2;  // 0..1 -> 32 rows each
    int wn = wid & 3;   // 0..3 -> 32 cols each
    int m0 = blockIdx.y * BMT;
    int n0 = blockIdx.x * BN;

    const char* Ahb = (const char*)Ah_g + ((long long)m0 * K) * 2;
    const char* Alb = (const char*)Al_g + ((long long)m0 * K) * 2;
    const char* Bhb = (const char*)Bh_g + ((long long)n0 * K) * 2;
    const char* Blb = (const char*)Bl_g + ((long long)n0 * K) * 2;
    const long long rowstride = (long long)K * 2;

    float acc[2][4][4];
#pragma unroll
    for (int i = 0; i < 2; i++)
#pragma unroll
        for (int j = 0; j < 4; j++)
#pragma unroll
            for (int r = 0; r < 4; r++) acc[i][j][r] = 0.0f;

    const int lrow = lane & 15;
    const int lhalf = lane >> 4;
    const int T = K / BK;

    int rowa[2], cba[2];
    uint32_t offa[2];
#pragma unroll
    for (int i = 0; i < 2; i++) {
        int ck = i * 256 + tid;
        rowa[i] = ck >> 3;
        cba[i] = (ck & 7) * 16;
        offa[i] = SWZ128((uint32_t)(rowa[i] * 128 + cba[i]));
    }
    int rowb[4], cbb[4];
    uint32_t offb[4];
#pragma unroll
    for (int i = 0; i < 4; i++) {
        int ck = i * 256 + tid;
        rowb[i] = ck >> 3;
        cbb[i] = (ck & 7) * 16;
        offb[i] = SWZ128((uint32_t)(rowb[i] * 128 + cbb[i]));
    }

#define LOAD_STAGE(t, s)                                                \
    do {                                                                \
        uint32_t stg = sb + (s) * GSTG;                                 \
        long long kb = (long long)(t) * (BK * 2);                       \
        _Pragma("unroll") for (int i = 0; i < 2; i++) {                 \
            long long src = rowa[i] * rowstride + kb + cba[i];          \
            CP_ASYNC16(stg + offa[i], Ahb + src);                       \
            CP_ASYNC16(stg + GOFF_AL + offa[i], Alb + src);             \
        }                                                               \
        _Pragma("unroll") for (int i = 0; i < 4; i++) {                 \
            long long src = rowb[i] * rowstride + kb + cbb[i];          \
            CP_ASYNC16(stg + GOFF_BH + offb[i], Bhb + src);             \
            CP_ASYNC16(stg + GOFF_BL + offb[i], Blb + src);             \
        }                                                               \
    } while (0)

    LOAD_STAGE(0, 0);
    CP_COMMIT;

    for (int t = 0; t < T; t++) {
        if (t + 1 < T) {
            LOAD_STAGE(t + 1, (t + 1) & 1);
            CP_COMMIT;
            CP_WAIT(1);
        } else {
            CP_WAIT(0);
        }
        __syncthreads();
        uint32_t stg = sb + (t & 1) * GSTG;
#pragma unroll
        for (int ks = 0; ks < 4; ks++) {
            int kb = ks * 32 + lhalf * 16;
            uint32_t ah[2][4], al[2][4], bh[2][4], bl[2][4];
#pragma unroll
            for (int mt = 0; mt < 2; mt++) {
                int r = wm * 32 + mt * 16 + lrow;
                uint32_t off = SWZ128((uint32_t)(r * 128 + kb));
                LDSM_X4(ah[mt], stg + off);
                LDSM_X4(al[mt], stg + GOFF_AL + off);
            }
#pragma unroll
            for (int g2 = 0; g2 < 2; g2++) {
                int r = wn * 32 + g2 * 16 + lrow;
                uint32_t off = SWZ128((uint32_t)(r * 128 + kb));
                LDSM_X4(bh[g2], stg + GOFF_BH + off);
                LDSM_X4(bl[g2], stg + GOFF_BL + off);
            }
#pragma unroll
            for (int mt = 0; mt < 2; mt++)
#pragma unroll
                for (int j = 0; j < 4; j++) {
                    uint32_t b0h = bh[j >> 1][j & 1], b1h = bh[j >> 1][(j & 1) + 2];
                    uint32_t b0l = bl[j >> 1][j & 1], b1l = bl[j >> 1][(j & 1) + 2];
                    MMA_BF16(acc[mt][j], ah[mt], b0h, b1h);
                    MMA_BF16(acc[mt][j], ah[mt], b0l, b1l);
                    MMA_BF16(acc[mt][j], al[mt], b0h, b1h);
                }
        }
        __syncthreads();
    }

    // ---- epilogue ----
    int g = lane >> 2;
    int tig = lane & 3;

    const float* bias = b0;
    __nv_bfloat16 *Poh = P0h, *Pol = P0l;
    int ncol0 = n0;
    int mat = 0;
    if (EPI == 0) {
        mat = n0 / 768;
        ncol0 = n0 % 768;
        bias = (mat == 0) ? b0 : ((mat == 1) ? b1 : b2);
        Poh = (mat == 0) ? P0h : ((mat == 1) ? P1h : P2h);
        Pol = (mat == 0) ? P0l : ((mat == 1) ? P1l : P2l);
    }
    const int ost = (EPI == 0) ? 768 : Nst;

#pragma unroll
    for (int mt = 0; mt < 2; mt++) {
#pragma unroll
        for (int j = 0; j < 4; j++) {
            int colrel = ncol0 + wn * 32 + j * 8 + tig * 2;
            float bia0 = bias[colrel], bia1 = bias[colrel + 1];
#pragma unroll
            for (int half = 0; half < 2; half++) {
                int row = m0 + wm * 32 + mt * 16 + g + half * 8;
                long long rb = (long long)row * ost + colrel;
                float u0 = acc[mt][j][half * 2 + 0] + bia0;
                float u1 = acc[mt][j][half * 2 + 1] + bia1;
                if (EPI == 0) {
                    if (mat == 0) {
                        u0 *= QSC;
                        u1 *= QSC;
                    }
                    split_pair(u0, u1, Poh + rb, Pol + rb);
                } else if (EPI == 1) {
                    u0 = 0.5f * u0 * (1.0f + erff(u0 * 0.70710678118654752f));
                    u1 = 0.5f * u1 * (1.0f + erff(u1 * 0.70710678118654752f));
                    split_pair(u0, u1, Poh + rb, Pol + rb);
                } else {
                    u0 += resid[rb];
                    u1 += resid[rb + 1];
                    *(float2*)(&C0[rb]) = make_float2(u0, u1);
                }
            }
        }
    }
}

// ================= tensor-core sliding-window attention =================
// CTA = 128 query rows x head; grid (32, 12). 8 warps x 16 rows.
// Window: 640 keys (10 tiles of 64) starting at q0g - W. smem 96KB, 2 CTAs/SM.
#define AQR 128
#define AKT 64
#define ANT 10
#define AST_BASE 32768
#define ATT_SMEM (32768 + 2 * 32768)

__global__ __launch_bounds__(256, 2) void attn_tc(
    const __nv_bfloat16* __restrict__ qh, const __nv_bfloat16* __restrict__ ql,
    const __nv_bfloat16* __restrict__ kh, const __nv_bfloat16* __restrict__ kl,
    const __nv_bfloat16* __restrict__ vh, const __nv_bfloat16* __restrict__ vl,
    __nv_bfloat16* __restrict__ aoh, __nv_bfloat16* __restrict__ aol) {
    extern __shared__ char smem[];
    uint32_t sb = smem_u32(smem);
    int tid = threadIdx.x;
    int lane = tid & 31;
    int wid = tid >> 5;
    int c = blockIdx.x;
    int h = blockIdx.y;
    const int q0g = c * AQR;
    const int cbase = q0g - W;  // window key 0 at q0g - 256 (FIXED: was q0g - 384)
    const int lrow = lane & 15;
    const int lhalf = lane >> 4;
    const int wr0 = wid * 16;

    // ---- load Q planes (128 rows x 128B each) ----
#pragma unroll
    for (int i = 0; i < 4; i++) {
        int id = i * 256 + tid;
        int row = id >> 3;
        int cb = (id & 7) * 16;
        long long gsrc = ((long long)(q0g + row) * D + h * DH) * 2 + cb;
        uint32_t dst = sb + SWZ128((uint32_t)(row * 128 + cb));
        CP_ASYNC16(dst, (const char*)qh + gsrc);
        CP_ASYNC16(dst + 16384, (const char*)ql + gsrc);
    }

#define ATT_LOAD(kt, s)                                                               \
    do {                                                                              \
        uint32_t stb = sb + AST_BASE + (s) * 32768;                                   \
        _Pragma("unroll") for (int pl_ = 0; pl_ < 4; pl_++) {                         \
            const char* gp = (pl_ == 0)   ? (const char*)kh                           \
                             : (pl_ == 1) ? (const char*)kl                           \
                             : (pl_ == 2) ? (const char*)vh                           \
                                          : (const char*)vl;                          \
            _Pragma("unroll") for (int j_ = 0; j_ < 2; j_++) {                        \
                int rem = j_ * 256 + tid;                                             \
                int row = rem >> 3;                                                   \
                int cb = (rem & 7) * 16;                                              \
                int kg = cbase + (kt) * AKT + row;                                    \
                int ok = (kg >= 0 && kg < S);                                         \
                int kgc = ok ? kg : 0;                                                \
                long long gsrc = ((long long)kgc * D + h * DH) * 2 + cb;              \
                CP_ASYNC16Z(stb + pl_ * 8192 + SWZ128((uint32_t)(row * 128 + cb)),    \
                            gp + gsrc, ok ? 16 : 0);                                  \
            }                                                                         \
        }                                                                             \
    } while (0)

    ATT_LOAD(0, 0);
    CP_COMMIT;

    float acc[8][4];
#pragma unroll
    for (int nf = 0; nf < 8; nf++)
#pragma unroll
        for (int e = 0; e < 4; e++) acc[nf][e] = 0.0f;
    float mrow[2] = {-1e30f, -1e30f};
    float lrowv[2] = {0.0f, 0.0f};

    for (int kt = 0; kt < ANT; kt++) {
        if (kt + 1 < ANT) {
            ATT_LOAD(kt + 1, (kt + 1) & 1);
            CP_COMMIT;
            CP_WAIT(1);
        } else {
            CP_WAIT(0);
        }
        __syncthreads();
        int jg0 = kt * AKT;
        bool active = (jg0 + AKT > wr0) && (jg0 <= wr0 + 15 + 2 * W);
        if (active) {
            uint32_t stb = sb + AST_BASE + (kt & 1) * 32768;
            uint32_t KH = stb, KL = stb + 8192, VH = stb + 16384, VL = stb + 24576;

            // ---- scores ----
            float sf[8][4];
#pragma unroll
            for (int nf = 0; nf < 8; nf++)
#pragma unroll
                for (int e = 0; e < 4; e++) sf[nf][e] = 0.0f;

#pragma unroll
            for (int ks = 0; ks < 4; ks++) {
                int kb = ks * 32 + lhalf * 16;
                uint32_t qhf[4], qlf[4];
                uint32_t qoff = SWZ128((uint32_t)((wr0 + lrow) * 128 + kb));
                LDSM_X4(qhf, sb + qoff);
                LDSM_X4(qlf, sb + 16384 + qoff);
#pragma unroll
                for (int nf2 = 0; nf2 < 4; nf2++) {
                    uint32_t khf[4], klf[4];
                    uint32_t off = SWZ128((uint32_t)((nf2 * 16 + lrow) * 128 + kb));
                    LDSM_X4(khf, KH + off);
                    LDSM_X4(klf, KL + off);
#pragma unroll
                    for (int hf = 0; hf < 2; hf++) {
                        int nf = nf2 * 2 + hf;
                        uint32_t b0h = khf[hf], b1h = khf[hf + 2];
                        uint32_t b0l = klf[hf], b1l = klf[hf + 2];
                        MMA_BF16(sf[nf], qhf, b0h, b1h);
                        MMA_BF16(sf[nf], qhf, b0l, b1l);
                        MMA_BF16(sf[nf], qlf, b0h, b1h);
                    }
                }
            }

            // ---- mask + online softmax ----
            int rA = wr0 + (lane >> 2);
            int rB = rA + 8;
#pragma unroll
            for (int nf = 0; nf < 8; nf++)
#pragma unroll
                for (int e = 0; e < 4; e++) {
                    int col = jg0 + nf * 8 + (lane & 3) * 2 + (e & 1);
                    int row = (e < 2) ? rA : rB;
                    int kg = cbase + col;
                    bool ok = (col >= row) && (col <= row + 2 * W) && (kg >= 0) && (kg < S);
                    if (!ok) sf[nf][e] = -1e30f;
                }
            float mA = -1e30f, mB = -1e30f;
#pragma unroll
            for (int nf = 0; nf < 8; nf++) {
                mA = fmaxf(mA, fmaxf(sf[nf][0], sf[nf][1]));
                mB = fmaxf(mB, fmaxf(sf[nf][2], sf[nf][3]));
            }
            mA = fmaxf(mA, __shfl_xor_sync(0xffffffffu, mA, 1));
            mA = fmaxf(mA, __shfl_xor_sync(0xffffffffu, mA, 2));
            mB = fmaxf(mB, __shfl_xor_sync(0xffffffffu, mB, 1));
            mB = fmaxf(mB, __shfl_xor_sync(0xffffffffu, mB, 2));
            float mnA = fmaxf(mrow[0], mA);
            float mnB = fmaxf(mrow[1], mB);
            float scA = exp2f(mrow[0] - mnA);
            float scB = exp2f(mrow[1] - mnB);
            float sumA = 0.0f, sumB = 0.0f;
#pragma unroll
            for (int nf = 0; nf < 8; nf++) {
                float p0 = exp2f(sf[nf][0] - mnA);
                float p1 = exp2f(sf[nf][1] - mnA);
                float p2 = exp2f(sf[nf][2] - mnB);
                float p3 = exp2f(sf[nf][3] - mnB);
                sf[nf][0] = p0;
                sf[nf][1] = p1;
                sf[nf][2] = p2;
                sf[nf][3] = p3;
                sumA += p0 + p1;
                sumB += p2 + p3;
            }
            sumA += __shfl_xor_sync(0xffffffffu, sumA, 1);
            sumA += __shfl_xor_sync(0xffffffffu, sumA, 2);
            sumB += __shfl_xor_sync(0xffffffffu, sumB, 1);
            sumB += __shfl_xor_sync(0xffffffffu, sumB, 2);
            lrowv[0] = lrowv[0] * scA + sumA;
            lrowv[1] = lrowv[1] * scB + sumB;
#pragma unroll
            for (int of = 0; of < 8; of++) {
                acc[of][0] *= scA;
                acc[of][1] *= scA;
                acc[of][2] *= scB;
                acc[of][3] *= scB;
            }
            mrow[0] = mnA;
            mrow[1] = mnB;

            // ---- P x V ----
#pragma unroll
            for (int ks2 = 0; ks2 < 4; ks2++) {
                const float* s0 = sf[2 * ks2];
                const float* s1 = sf[2 * ks2 + 1];
                uint32_t pah[4], pal[4];
                pack_hl(s0[0], s0[1], pah[0], pal[0]);
                pack_hl(s0[2], s0[3], pah[1], pal[1]);
                pack_hl(s1[0], s1[1], pah[2], pal[2]);
                pack_hl(s1[2], s1[3], pah[3], pal[3]);
#pragma unroll
                for (int vf2 = 0; vf2 < 4; vf2++) {
                    uint32_t vhf[4], vlf[4];
                    uint32_t off =
                        SWZ128((uint32_t)((ks2 * 16 + lrow) * 128 + vf2 * 32 + lhalf * 16));
                    LDSM_X4_T(vhf, VH + off);
                    LDSM_X4_T(vlf, VL + off);
#pragma unroll
                    for (int hf = 0; hf < 2; hf++) {
                        int nf = vf2 * 2 + hf;
                        uint32_t b0h = vhf[hf * 2], b1h = vhf[hf * 2 + 1];
                        uint32_t b0l = vlf[hf * 2], b1l = vlf[hf * 2 + 1];
                        MMA_BF16(acc[nf], pah, b0h, b1h);
                        MMA_BF16(acc[nf], pah, b0l, b1l);
                        MMA_BF16(acc[nf], pal, b0h, b1h);
                    }
                }
            }
        }
        __syncthreads();
    }

    // ---- epilogue ----
    {
        float invA = 1.0f / lrowv[0];
        float invB = 1.0f / lrowv[1];
        int rA = wr0 + (lane >> 2);
        long long baseA = (long long)(q0g + rA) * D + h * DH;
        long long baseB = baseA + 8LL * D;
#pragma unroll
        for (int nf = 0; nf < 8; nf++) {
            int col = nf * 8 + (lane & 3) * 2;
            split_pair(acc[nf][0] * invA, acc[nf][1] * invA, aoh + baseA + col,
                       aol + baseA + col);
            split_pair(acc[nf][2] * invB, acc[nf][3] * invB, aoh + baseB + col,
                       aol + baseB + col);
        }
    }
}

__global__ void head_kernel(const float* __restrict__ hrow, const float* __restrict__ w,
                            const float* __restrict__ b, float* __restrict__ out) {
    int o = threadIdx.x;
    float acc = b[o];
    for (int d = 0; d < D; d++) acc += hrow[d] * w[d * OUT + o];
    out[o] = acc;
}

// ================= launch =================
extern "C" void kernel_launch(void* const* d_in, const int* in_sizes, int n_in,
                              void* d_out, int out_size) {
    (void)in_sizes; (void)n_in; (void)out_size;
    const int* x = (const int*)d_in[0];
    const float* word_emb = (const float*)d_in[1];
    const float* pos_emb = (const float*)d_in[2];
    const float* tt_emb = (const float*)d_in[3];
    const float* elg = (const float*)d_in[4];
    const float* elb = (const float*)d_in[5];
    const float* Wq = (const float*)d_in[6];
    const float* bq = (const float*)d_in[7];
    const float* Wk = (const float*)d_in[8];
    const float* bk = (const float*)d_in[9];
    const float* Wv = (const float*)d_in[10];
    const float* bv = (const float*)d_in[11];
    const float* Wo = (const float*)d_in[12];
    const float* bo = (const float*)d_in[13];
    const float* g1 = (const float*)d_in[14];
    const float* b1 = (const float*)d_in[15];
    const float* Wi = (const float*)d_in[16];
    const float* bi = (const float*)d_in[17];
    const float* Wd = (const float*)d_in[18];
    const float* bd = (const float*)d_in[19];
    const float* g2 = (const float*)d_in[20];
    const float* b2 = (const float*)d_in[21];
    const float* ow = (const float*)d_in[22];
    const float* ob = (const float*)d_in[23];
    float* out = (float*)d_out;

    float *h, *t;
    __nv_bfloat16 *qh, *ql, *kh, *kl, *vh, *vl, *hh, *hl, *ah, *al, *fh, *fl, *wTh, *wTl;
    cudaGetSymbolAddress((void**)&h, g_h);
    cudaGetSymbolAddress((void**)&t, g_t);
    cudaGetSymbolAddress((void**)&qh, g_qh);
    cudaGetSymbolAddress((void**)&ql, g_ql);
    cudaGetSymbolAddress((void**)&kh, g_kh);
    cudaGetSymbolAddress((void**)&kl, g_kl);
    cudaGetSymbolAddress((void**)&vh, g_vh);
    cudaGetSymbolAddress((void**)&vl, g_vl);
    cudaGetSymbolAddress((void**)&hh, g_hh);
    cudaGetSymbolAddress((void**)&hl, g_hl);
    cudaGetSymbolAddress((void**)&ah, g_ah);
    cudaGetSymbolAddress((void**)&al, g_al);
    cudaGetSymbolAddress((void**)&fh, g_fh);
    cudaGetSymbolAddress((void**)&fl, g_fl);
    cudaGetSymbolAddress((void**)&wTh, g_wTh);
    cudaGetSymbolAddress((void**)&wTl, g_wTl);

    cudaFuncSetAttribute(mgemm<0>, cudaFuncAttributeMaxDynamicSharedMemorySize, SMEM_G);
    cudaFuncSetAttribute(mgemm<1>, cudaFuncAttributeMaxDynamicSharedMemorySize, SMEM_G);
    cudaFuncSetAttribute(mgemm<2>, cudaFuncAttributeMaxDynamicSharedMemorySize, SMEM_G);
    cudaFuncSetAttribute(attn_tc, cudaFuncAttributeMaxDynamicSharedMemorySize, ATT_SMEM);

    {
        dim3 tb(32, 8);
        tsp_dd<<<dim3(D / 32, D / 32, 4 * L), tb>>>(Wq, Wk, Wv, Wo, wTh, wTl);
        tsp_wi<<<dim3(FF / 32, D / 32, L), tb>>>(Wi, wTh, wTl);
        tsp_wd<<<dim3(D / 32, FF / 32, L), tb>>>(Wd, wTh, wTl);
    }

    emb_kernel<<<S, 256>>>(x, word_emb, pos_emb, tt_emb, t);
    ln_kernel<<<S, 256>>>(t, elg, elb, h, hh, hl);

    dim3 gqkv(2304 / BN, S / BMT);  // 18 x 64
    dim3 gproj(768 / BN, S / BMT);  // 6 x 64
    dim3 gff1(FF / BN, S / BMT);    // 24 x 64
    dim3 gattn(S / AQR, H);         // 32 x 12

    for (int l = 0; l < L; l++) {
        long long lb = (long long)l * WT_PER_LAYER;

        mgemm<0><<<gqkv, 256, SMEM_G>>>(hh, hl, wTh + lb + OQKV, wTl + lb + OQKV,
                                        bq + l * D, bk + l * D, bv + l * D, nullptr,
                                        nullptr, qh, ql, kh, kl, vh, vl, 768, D);

        attn_tc<<<gattn, 256, ATT_SMEM>>>(qh, ql, kh, kl, vh, vl, ah, al);

        mgemm<2><<<gproj, 256, SMEM_G>>>(ah, al, wTh + lb + OO, wTl + lb + OO,
                                         bo + l * D, nullptr, nullptr, h, t,
                                         nullptr, nullptr, nullptr, nullptr, nullptr, nullptr,
                                         768, D);
        ln_kernel<<<S, 256>>>(t, g1 + l * D, b1 + l * D, h, hh, hl);

        mgemm<1><<<gff1, 256, SMEM_G>>>(hh, hl, wTh + lb + OI, wTl + lb + OI,
                                        bi + l * FF, nullptr, nullptr, nullptr, nullptr,
                                        fh, fl, nullptr, nullptr, nullptr, nullptr, FF, D);
        mgemm<2><<<gproj, 256, SMEM_G>>>(fh, fl, wTh + lb + OD, wTl + lb + OD,
                                         bd + l * D, nullptr, nullptr, h, t,
                                         nullptr, nullptr, nullptr, nullptr, nullptr, nullptr,
                                         768, FF);
        ln_kernel<<<S, 256>>>(t, g2 + l * D, b2 + l * D, h, hh, hl);
    }

    head_kernel<<<1, 256>>>(h, ow, ob, out);
}